// round 8
// baseline (speedup 1.0000x reference)
#include <cuda_runtime.h>
#include <cuda_fp16.h>
#include <math.h>
#include <stdint.h>

#define B_   2
#define T_   2048
#define C_   1024
#define H_   16
#define HD_  64
#define NTOK (B_*T_)   // 4096

// ---------------------------------------------------------------------------
// Scratch (__device__ globals; allocation-free rule)
// ---------------------------------------------------------------------------
__device__ __half g_qh[NTOK*C_], g_ql[NTOK*C_];
__device__ __half g_kh[NTOK*C_], g_kl[NTOK*C_];
__device__ __half g_vh[NTOK*C_], g_vl[NTOK*C_];
__device__ __half g_xh[NTOK*C_], g_xl[NTOK*C_];   // x hi/lo, later y hi/lo
__device__ __half g_wh[4*C_*C_], g_wl[4*C_*C_];   // Wq|Wk|Wv|Wp hi/lo

// ---------------------------------------------------------------------------
// PTX helpers (sm_80-baseline only — harness compiles for sm_103 w/o 'a')
// ---------------------------------------------------------------------------
__device__ __forceinline__ uint32_t smem_u32(const void* p) {
    uint32_t a;
    asm("{ .reg .u64 t; cvta.to.shared.u64 t, %1; cvt.u32.u64 %0, t; }"
        : "=r"(a) : "l"(p));
    return a;
}
__device__ __forceinline__ void cp16(uint32_t dst, const void* src) {
    asm volatile("cp.async.ca.shared.global [%0], [%1], 16;" :: "r"(dst), "l"(src));
}
#define CP_COMMIT()  asm volatile("cp.async.commit_group;" ::: "memory")
#define CP_WAIT(N)   asm volatile("cp.async.wait_group " #N ";" ::: "memory")

#define LDMX4(r, addr) \
    asm volatile("ldmatrix.sync.aligned.m8n8.x4.shared.b16 {%0,%1,%2,%3}, [%4];" \
        : "=r"((r)[0]), "=r"((r)[1]), "=r"((r)[2]), "=r"((r)[3]) : "r"(addr))
#define LDMX4T(r, addr) \
    asm volatile("ldmatrix.sync.aligned.m8n8.x4.trans.shared.b16 {%0,%1,%2,%3}, [%4];" \
        : "=r"((r)[0]), "=r"((r)[1]), "=r"((r)[2]), "=r"((r)[3]) : "r"(addr))

#define MMA16816(d, a, b) \
    asm volatile("mma.sync.aligned.m16n8k16.row.col.f32.f16.f16.f32 " \
        "{%0,%1,%2,%3}, {%4,%5,%6,%7}, {%8,%9}, {%0,%1,%2,%3};" \
        : "+f"((d)[0]), "+f"((d)[1]), "+f"((d)[2]), "+f"((d)[3]) \
        : "r"((a)[0]), "r"((a)[1]), "r"((a)[2]), "r"((a)[3]), \
          "r"((b)[0]), "r"((b)[1]))

__device__ __forceinline__ float ex2(float x) {
    float r;
    asm("ex2.approx.ftz.f32 %0, %1;" : "=f"(r) : "f"(x));
    return r;
}
__device__ __forceinline__ uint32_t packh2(float a, float b) {
    __half2 h = __floats2half2_rn(a, b);
    return *reinterpret_cast<uint32_t*>(&h);
}

// ---------------------------------------------------------------------------
// fp32 -> (hi, lo) fp16 split conversions
// ---------------------------------------------------------------------------
__global__ void __launch_bounds__(256)
cvt_split(const float4* __restrict__ src, __half2* __restrict__ hi,
          __half2* __restrict__ lo, int n4)
{
    int i = blockIdx.x * blockDim.x + threadIdx.x;
    if (i >= n4) return;
    float4 f = src[i];
    __half2 h01 = __floats2half2_rn(f.x, f.y);
    __half2 h23 = __floats2half2_rn(f.z, f.w);
    float2 b01 = __half22float2(h01);
    float2 b23 = __half22float2(h23);
    hi[2*i]   = h01;  hi[2*i+1] = h23;
    lo[2*i]   = __floats2half2_rn(f.x - b01.x, f.y - b01.y);
    lo[2*i+1] = __floats2half2_rn(f.z - b23.x, f.w - b23.y);
}

__global__ void __launch_bounds__(256)
cvt_split_w4(const float4* __restrict__ s0, const float4* __restrict__ s1,
             const float4* __restrict__ s2, const float4* __restrict__ s3,
             __half2* __restrict__ hi, __half2* __restrict__ lo)
{
    const int NW4 = C_ * C_ / 4;   // 262144 = 2^18
    int i = blockIdx.x * blockDim.x + threadIdx.x;
    if (i >= 4 * NW4) return;
    int mid = i >> 18;
    int off = i & (NW4 - 1);
    const float4* src = (mid == 0) ? s0 : (mid == 1) ? s1 : (mid == 2) ? s2 : s3;
    float4 f = src[off];
    __half2 h01 = __floats2half2_rn(f.x, f.y);
    __half2 h23 = __floats2half2_rn(f.z, f.w);
    float2 b01 = __half22float2(h01);
    float2 b23 = __half22float2(h23);
    hi[2*i]   = h01;  hi[2*i+1] = h23;
    lo[2*i]   = __floats2half2_rn(f.x - b01.x, f.y - b01.y);
    lo[2*i+1] = __floats2half2_rn(f.z - b23.x, f.w - b23.y);
}

// ---------------------------------------------------------------------------
// HMMA GEMM, split-fp16 3-term. CTA tile 128x128, BK=64, 2-stage cp.async.
// MODE 0: fp32 out [m][n].  MODE 1: merged QKV (N=3072), head-split hi/lo out.
// ---------------------------------------------------------------------------
#define GEMM_SMEM (2*65536)

__device__ __forceinline__ void load_stage(
    uint32_t sb,
    const __half* __restrict__ Ah, const __half* __restrict__ Al,
    const __half* __restrict__ Bh, const __half* __restrict__ Bl,
    int m0, int n0, int k0, int tid)
{
    #pragma unroll
    for (int i = 0; i < 4; i++) {
        int idx = tid + i * 256;
        int r = idx >> 3, u = idx & 7;
        uint32_t doff = r * 128 + ((u ^ (r & 7)) << 4);
        size_t aoff = (size_t)(m0 + r) * C_ + k0 + u * 8;
        size_t boff = (size_t)(n0 + r) * C_ + k0 + u * 8;
        cp16(sb +         doff, Ah + aoff);
        cp16(sb + 16384 + doff, Al + aoff);
        cp16(sb + 32768 + doff, Bh + boff);
        cp16(sb + 49152 + doff, Bl + boff);
    }
}

template<int MODE>
__global__ void __launch_bounds__(256)
gemm_hmma(const __half* __restrict__ Ah, const __half* __restrict__ Al,
          const __half* __restrict__ Bh, const __half* __restrict__ Bl,
          const float* __restrict__ b0, const float* __restrict__ b1,
          const float* __restrict__ b2,
          float* __restrict__ outf,
          __half* __restrict__ o0h, __half* __restrict__ o0l,
          __half* __restrict__ o1h, __half* __restrict__ o1l,
          __half* __restrict__ o2h, __half* __restrict__ o2l,
          float scale0)
{
    extern __shared__ __align__(1024) char smem[];
    uint32_t sbase = smem_u32(smem);
    const int tid  = threadIdx.x;
    const int lane = tid & 31;
    const int warp = tid >> 5;
    const int wm   = warp >> 2;
    const int wn   = warp & 3;
    const int m0   = blockIdx.y * 128;
    const int n0   = blockIdx.x * 128;

    float acc[4][4][4];
    #pragma unroll
    for (int i = 0; i < 4; i++)
        #pragma unroll
        for (int j = 0; j < 4; j++)
            #pragma unroll
            for (int k = 0; k < 4; k++) acc[i][j][k] = 0.f;

    load_stage(sbase, Ah, Al, Bh, Bl, m0, n0, 0, tid);
    CP_COMMIT();

    for (int kt = 0; kt < 16; kt++) {
        if (kt + 1 < 16) {
            load_stage(sbase + ((kt + 1) & 1) * 65536, Ah, Al, Bh, Bl,
                       m0, n0, (kt + 1) * 64, tid);
            CP_COMMIT();
            CP_WAIT(1);
        } else {
            CP_WAIT(0);
        }
        __syncthreads();

        uint32_t sb = sbase + (kt & 1) * 65536;

        #pragma unroll
        for (int ks = 0; ks < 4; ks++) {
            uint32_t ah[4][4], al[4][4];
            {
                int arow = wm * 64 + (lane & 15);
                int aku  = ks * 2 + (lane >> 4);
                #pragma unroll
                for (int mi = 0; mi < 4; mi++) {
                    int r = arow + mi * 16;
                    uint32_t addr = sb + r * 128 + ((aku ^ (r & 7)) << 4);
                    LDMX4(ah[mi], addr);
                    LDMX4(al[mi], addr + 16384);
                }
            }
            uint32_t bhf[4][2], blf[4][2];
            {
                int brow0 = wn * 32 + ((lane >> 4) << 3) + (lane & 7);
                int bku   = ks * 2 + ((lane >> 3) & 1);
                #pragma unroll
                for (int nj2 = 0; nj2 < 2; nj2++) {
                    int r = brow0 + nj2 * 16;
                    uint32_t addr = sb + 32768 + r * 128 + ((bku ^ (r & 7)) << 4);
                    uint32_t t[4];
                    LDMX4(t, addr);
                    bhf[2*nj2][0] = t[0]; bhf[2*nj2][1] = t[1];
                    bhf[2*nj2+1][0] = t[2]; bhf[2*nj2+1][1] = t[3];
                    LDMX4(t, addr + 16384);
                    blf[2*nj2][0] = t[0]; blf[2*nj2][1] = t[1];
                    blf[2*nj2+1][0] = t[2]; blf[2*nj2+1][1] = t[3];
                }
            }
            #pragma unroll
            for (int mi = 0; mi < 4; mi++)
                #pragma unroll
                for (int nj = 0; nj < 4; nj++) {
                    MMA16816(acc[mi][nj], ah[mi], bhf[nj]);
                    MMA16816(acc[mi][nj], al[mi], bhf[nj]);
                    MMA16816(acc[mi][nj], ah[mi], blf[nj]);
                }
        }
        __syncthreads();
    }

    const int r0 = lane >> 2;
    const int c0 = (lane & 3) * 2;

    const float* bias;
    __half *oh, *ol;
    float scale = 1.0f;
    if (MODE == 1) {
        int mid = n0 >> 10;
        bias = (mid == 0) ? b0 : (mid == 1) ? b1 : b2;
        oh   = (mid == 0) ? o0h : (mid == 1) ? o1h : o2h;
        ol   = (mid == 0) ? o0l : (mid == 1) ? o1l : o2l;
        if (mid == 0) scale = scale0;
    } else {
        bias = b0;
    }

    #pragma unroll
    for (int mi = 0; mi < 4; mi++) {
        #pragma unroll
        for (int nj = 0; nj < 4; nj++) {
            int nl = (n0 & 1023) + wn * 32 + nj * 8 + c0;
            float2 bv = *(const float2*)(bias + nl);
            #pragma unroll
            for (int h2 = 0; h2 < 2; h2++) {
                int m = m0 + wm * 64 + mi * 16 + r0 + h2 * 8;
                float v0 = acc[mi][nj][h2*2+0] + bv.x;
                float v1 = acc[mi][nj][h2*2+1] + bv.y;
                if (MODE == 0) {
                    float2 o = {v0, v1};
                    *(float2*)(outf + (size_t)m * C_ + nl) = o;
                } else {
                    v0 *= scale; v1 *= scale;
                    __half2 hh = __floats2half2_rn(v0, v1);
                    float2 hf = __half22float2(hh);
                    __half2 ll = __floats2half2_rn(v0 - hf.x, v1 - hf.y);
                    int b = m >> 11, t = m & (T_ - 1);
                    int h = nl >> 6, d = nl & 63;
                    size_t idx = (((size_t)(b * H_ + h)) * T_ + t) * HD_ + d;
                    *(__half2*)(oh + idx) = hh;
                    *(__half2*)(ol + idx) = ll;
                }
            }
        }
    }
}

// ---------------------------------------------------------------------------
// Tensor-core flash attention v4: 4 warps x 32 q-rows = 128 q-rows per CTA,
// 64-key blocks. K/V LDSM amortized over 2 m-tiles; 2x accumulator ILP.
// smem 80 KB: Q 32K | K 2x16K (double-buf) | V 16K (single-buf) -> 2 CTAs/SM.
// ---------------------------------------------------------------------------
#define AT_SMEM 81920

__global__ void __launch_bounds__(128, 2) attn_tc()
{
    extern __shared__ __align__(1024) char smem[];
    uint32_t sb = smem_u32(smem);
    const int tid  = threadIdx.x;
    const int lane = tid & 31;
    const int warp = tid >> 5;                              // 0..3
    const int qt   = (int)gridDim.x - 1 - (int)blockIdx.x;  // heavy first (128-row tiles)
    const int bh   = blockIdx.y;
    const int nkb  = 2 * qt + 2;                            // 64-key blocks

    const __half* qhp = g_qh + ((size_t)bh * T_ + qt * 128) * HD_;
    const __half* qlp = g_ql + ((size_t)bh * T_ + qt * 128) * HD_;
    const __half* khp = g_kh + (size_t)bh * T_ * HD_;
    const __half* klp = g_kl + (size_t)bh * T_ * HD_;
    const __half* vhp = g_vh + (size_t)bh * T_ * HD_;
    const __half* vlp = g_vl + (size_t)bh * T_ * HD_;

    // ---- group 1: Q (hi+lo), 128 rows, 2048 cp16 ----
    #pragma unroll
    for (int i = 0; i < 16; i++) {
        int idx = tid + i * 128;               // 0..2047
        int half_sel = idx >> 10;              // 0: hi, 1: lo
        int w = idx & 1023;
        int r = w >> 3, u = w & 7;
        uint32_t doff = half_sel * 16384u + r * 128 + ((u ^ (r & 7)) << 4);
        const __half* src = (half_sel ? qlp : qhp) + (size_t)r * HD_ + u * 8;
        cp16(sb + doff, src);
    }
    CP_COMMIT();

    // K stage loader (Kh+Kl = 16 KB)
    auto load_k = [&](int stage, int kb) {
        uint32_t st = sb + 32768 + stage * 16384;
        #pragma unroll
        for (int i = 0; i < 8; i++) {
            int idx = tid + i * 128;
            int half_sel = idx >> 9;
            int w = idx & 511;
            int r = w >> 3, u = w & 7;
            const __half* src = (half_sel ? klp : khp) + ((size_t)(kb * 64 + r)) * HD_ + u * 8;
            cp16(st + half_sel * 8192u + r * 128 + ((u ^ (r & 7)) << 4), src);
        }
    };
    // V loader (Vh+Vl = 16 KB, single buffer)
    auto load_v = [&](int kb) {
        uint32_t st = sb + 65536;
        #pragma unroll
        for (int i = 0; i < 8; i++) {
            int idx = tid + i * 128;
            int half_sel = idx >> 9;
            int w = idx & 511;
            int r = w >> 3, u = w & 7;
            const __half* src = (half_sel ? vlp : vhp) + ((size_t)(kb * 64 + r)) * HD_ + u * 8;
            cp16(st + half_sel * 8192u + r * 128 + ((u ^ (r & 7)) << 4), src);
        }
    };

    load_k(0, 0); CP_COMMIT();     // group 2
    load_v(0);    CP_COMMIT();     // group 3

    float o[2][8][4];
    #pragma unroll
    for (int mi = 0; mi < 2; mi++)
        #pragma unroll
        for (int j = 0; j < 8; j++)
            #pragma unroll
            for (int e = 0; e < 4; e++) o[mi][j][e] = 0.f;
    float mrow[2][2] = {{-1e30f, -1e30f}, {-1e30f, -1e30f}};
    float lrow[2][2] = {{0.f, 0.f}, {0.f, 0.f}};

    for (int kb = 0; kb < nkb; kb++) {
        if (kb + 1 < nkb) { load_k((kb + 1) & 1, kb + 1); CP_COMMIT(); CP_WAIT(1); }
        else              { CP_WAIT(0); }
        __syncthreads();

        const bool maskblk = (kb >= 2 * qt);          // last two blocks are partial
        const int  kloc    = (kb - 2 * qt) * 64;      // key offset rel. to q-tile base
        uint32_t stK = sb + 32768 + (kb & 1) * 16384;
        uint32_t sv  = sb + 65536;

        // ---- S = Q K^T (3-term split), ks-outer, 2 m-tiles per warp ----
        float s[2][8][4];
        #pragma unroll
        for (int mi = 0; mi < 2; mi++)
            #pragma unroll
            for (int j = 0; j < 8; j++)
                #pragma unroll
                for (int e = 0; e < 4; e++) s[mi][j][e] = 0.f;

        #pragma unroll
        for (int ks = 0; ks < 4; ks++) {
            uint32_t qh4[2][4], ql4[2][4];
            #pragma unroll
            for (int mi = 0; mi < 2; mi++) {
                int arow = warp * 32 + mi * 16 + (lane & 15);
                int u = ks * 2 + (lane >> 4);
                uint32_t qaddr = sb + arow * 128 + ((u ^ (arow & 7)) << 4);
                LDMX4(qh4[mi], qaddr);
                LDMX4(ql4[mi], qaddr + 16384);
            }
            #pragma unroll
            for (int g = 0; g < 4; g++) {
                if (!maskblk || kloc + 16 * g <= 32 * warp + 31) {
                    int brow = g * 16 + ((lane >> 4) << 3) + (lane & 7);
                    int bku  = ks * 2 + ((lane >> 3) & 1);
                    uint32_t addr = stK + brow * 128 + ((bku ^ (brow & 7)) << 4);
                    uint32_t kh4[4], kl4[4];
                    LDMX4(kh4, addr);
                    LDMX4(kl4, addr + 8192);
                    #pragma unroll
                    for (int mi = 0; mi < 2; mi++) {
                        if (!maskblk || kloc + 16 * g <= 32 * warp + mi * 16 + 15) {
                            MMA16816(s[mi][2*g],   qh4[mi], kh4);
                            MMA16816(s[mi][2*g],   ql4[mi], kh4);
                            MMA16816(s[mi][2*g],   qh4[mi], kl4);
                            MMA16816(s[mi][2*g+1], qh4[mi], kh4 + 2);
                            MMA16816(s[mi][2*g+1], ql4[mi], kh4 + 2);
                            MMA16816(s[mi][2*g+1], qh4[mi], kl4 + 2);
                        }
                    }
                }
            }
        }

        if (maskblk) {
            #pragma unroll
            for (int mi = 0; mi < 2; mi++) {
                int rbase = 32 * warp + 16 * mi + (lane >> 2);
                int cbase = kloc + 2 * (lane & 3);
                #pragma unroll
                for (int j = 0; j < 8; j++) {
                    int c = cbase + 8 * j;
                    if (c     > rbase)     s[mi][j][0] = -1e30f;
                    if (c + 1 > rbase)     s[mi][j][1] = -1e30f;
                    if (c     > rbase + 8) s[mi][j][2] = -1e30f;
                    if (c + 1 > rbase + 8) s[mi][j][3] = -1e30f;
                }
            }
        }

        // ---- online softmax (base-2; scale folded into Q) ----
        #pragma unroll
        for (int mi = 0; mi < 2; mi++) {
            float mloc0 = -1e30f, mloc1 = -1e30f;
            #pragma unroll
            for (int j = 0; j < 8; j++) {
                mloc0 = fmaxf(mloc0, fmaxf(s[mi][j][0], s[mi][j][1]));
                mloc1 = fmaxf(mloc1, fmaxf(s[mi][j][2], s[mi][j][3]));
            }
            #pragma unroll
            for (int off = 1; off < 4; off <<= 1) {
                mloc0 = fmaxf(mloc0, __shfl_xor_sync(0xffffffffu, mloc0, off));
                mloc1 = fmaxf(mloc1, __shfl_xor_sync(0xffffffffu, mloc1, off));
            }
            float mn0 = fmaxf(mrow[mi][0], mloc0);
            float mn1 = fmaxf(mrow[mi][1], mloc1);
            float cr0 = ex2(mrow[mi][0] - mn0);
            float cr1 = ex2(mrow[mi][1] - mn1);
            mrow[mi][0] = mn0; mrow[mi][1] = mn1;

            float sum0 = 0.f, sum1 = 0.f;
            #pragma unroll
            for (int j = 0; j < 8; j++) {
                s[mi][j][0] = ex2(s[mi][j][0] - mn0); sum0 += s[mi][j][0];
                s[mi][j][1] = ex2(s[mi][j][1] - mn0); sum0 += s[mi][j][1];
                s[mi][j][2] = ex2(s[mi][j][2] - mn1); sum1 += s[mi][j][2];
                s[mi][j][3] = ex2(s[mi][j][3] - mn1); sum1 += s[mi][j][3];
            }
            #pragma unroll
            for (int off = 1; off < 4; off <<= 1) {
                sum0 += __shfl_xor_sync(0xffffffffu, sum0, off);
                sum1 += __shfl_xor_sync(0xffffffffu, sum1, off);
            }
            lrow[mi][0] = lrow[mi][0] * cr0 + sum0;
            lrow[mi][1] = lrow[mi][1] * cr1 + sum1;

            #pragma unroll
            for (int j = 0; j < 8; j++) {
                o[mi][j][0] *= cr0; o[mi][j][1] *= cr0;
                o[mi][j][2] *= cr1; o[mi][j][3] *= cr1;
            }
        }

        // ---- O += P V (3-term split); per-(kk,mi) diag skip ----
        #pragma unroll
        for (int kk = 0; kk < 4; kk++) {
            if (!maskblk || kloc + 16 * kk <= 32 * warp + 31) {
                uint32_t ph[2][4], pl[2][4];
                #pragma unroll
                for (int mi = 0; mi < 2; mi++) {
                    if (!maskblk || kloc + 16 * kk <= 32 * warp + mi * 16 + 15) {
                        ph[mi][0] = packh2(s[mi][2*kk][0],   s[mi][2*kk][1]);
                        ph[mi][1] = packh2(s[mi][2*kk][2],   s[mi][2*kk][3]);
                        ph[mi][2] = packh2(s[mi][2*kk+1][0], s[mi][2*kk+1][1]);
                        ph[mi][3] = packh2(s[mi][2*kk+1][2], s[mi][2*kk+1][3]);
                        #pragma unroll
                        for (int e = 0; e < 4; e++) {
                            float2 f = __half22float2(*reinterpret_cast<__half2*>(&ph[mi][e]));
                            int j = 2*kk + (e >> 1);
                            int base = (e & 1) * 2;
                            pl[mi][e] = packh2(s[mi][j][base] - f.x, s[mi][j][base+1] - f.y);
                        }
                    }
                }
                int vrow = kk * 16 + ((lane >> 3) & 1) * 8 + (lane & 7);
                #pragma unroll
                for (int g = 0; g < 4; g++) {
                    int vu = 2 * g + (lane >> 4);
                    uint32_t addr = sv + vrow * 128 + ((vu ^ (vrow & 7)) << 4);
                    uint32_t vh4[4], vl4[4];
                    LDMX4T(vh4, addr);
                    LDMX4T(vl4, addr + 8192);
                    #pragma unroll
                    for (int mi = 0; mi < 2; mi++) {
                        if (!maskblk || kloc + 16 * kk <= 32 * warp + mi * 16 + 15) {
                            MMA16816(o[mi][2*g],   ph[mi], vh4);
                            MMA16816(o[mi][2*g],   pl[mi], vh4);
                            MMA16816(o[mi][2*g],   ph[mi], vl4);
                            MMA16816(o[mi][2*g+1], ph[mi], vh4 + 2);
                            MMA16816(o[mi][2*g+1], pl[mi], vh4 + 2);
                            MMA16816(o[mi][2*g+1], ph[mi], vl4 + 2);
                        }
                    }
                }
            }
        }
        __syncthreads();   // all warps done with V(kb)

        if (kb + 1 < nkb) { load_v(kb + 1); CP_COMMIT(); }   // hides under next QK
    }

    // ---- epilogue: y = O / l -> hi/lo halves into out-proj input buffers ----
    int b = bh >> 4;
    int h = bh & 15;
    int d0 = 2 * (lane & 3);
    #pragma unroll
    for (int mi = 0; mi < 2; mi++) {
        float inv0 = 1.0f / lrow[mi][0];
        float inv1 = 1.0f / lrow[mi][1];
        int t0 = qt * 128 + warp * 32 + mi * 16 + (lane >> 2);
        #pragma unroll
        for (int j = 0; j < 8; j++) {
            int d = 8 * j + d0;
            {
                float y0 = o[mi][j][0] * inv0, y1 = o[mi][j][1] * inv0;
                __half2 hh = __floats2half2_rn(y0, y1);
                float2 hf = __half22float2(hh);
                __half2 ll = __floats2half2_rn(y0 - hf.x, y1 - hf.y);
                size_t idx = ((size_t)(b * T_ + t0)) * C_ + h * HD_ + d;
                *(__half2*)(g_xh + idx) = hh;
                *(__half2*)(g_xl + idx) = ll;
            }
            {
                float y0 = o[mi][j][2] * inv1, y1 = o[mi][j][3] * inv1;
                __half2 hh = __floats2half2_rn(y0, y1);
                float2 hf = __half22float2(hh);
                __half2 ll = __floats2half2_rn(y0 - hf.x, y1 - hf.y);
                size_t idx = ((size_t)(b * T_ + t0 + 8)) * C_ + h * HD_ + d;
                *(__half2*)(g_xh + idx) = hh;
                *(__half2*)(g_xl + idx) = ll;
            }
        }
    }
}

// ---------------------------------------------------------------------------
extern "C" void kernel_launch(void* const* d_in, const int* in_sizes, int n_in,
                              void* d_out, int out_size)
{
    const float* x  = (const float*)d_in[0];
    const float* Wq = (const float*)d_in[1];
    const float* bq = (const float*)d_in[2];
    const float* Wk = (const float*)d_in[3];
    const float* bk = (const float*)d_in[4];
    const float* Wv = (const float*)d_in[5];
    const float* bv = (const float*)d_in[6];
    const float* Wp = (const float*)d_in[7];
    const float* bp = (const float*)d_in[8];
    float* out = (float*)d_out;

    __half *qh, *ql, *kh, *kl, *vh, *vl, *xh, *xl, *wh, *wl;
    cudaGetSymbolAddress((void**)&qh, g_qh);
    cudaGetSymbolAddress((void**)&ql, g_ql);
    cudaGetSymbolAddress((void**)&kh, g_kh);
    cudaGetSymbolAddress((void**)&kl, g_kl);
    cudaGetSymbolAddress((void**)&vh, g_vh);
    cudaGetSymbolAddress((void**)&vl, g_vl);
    cudaGetSymbolAddress((void**)&xh, g_xh);
    cudaGetSymbolAddress((void**)&xl, g_xl);
    cudaGetSymbolAddress((void**)&wh, g_wh);
    cudaGetSymbolAddress((void**)&wl, g_wl);

    cudaFuncSetAttribute(gemm_hmma<0>, cudaFuncAttributeMaxDynamicSharedMemorySize, GEMM_SMEM);
    cudaFuncSetAttribute(gemm_hmma<1>, cudaFuncAttributeMaxDynamicSharedMemorySize, GEMM_SMEM);
    cudaFuncSetAttribute(attn_tc, cudaFuncAttributeMaxDynamicSharedMemorySize, AT_SMEM);

    const int NX4 = NTOK * C_ / 4;     // 1M
    const int NW4 = C_ * C_ / 4;       // 256K
    cvt_split<<<(NX4 + 255)/256, 256>>>((const float4*)x, (__half2*)xh, (__half2*)xl, NX4);
    cvt_split_w4<<<(4*NW4 + 255)/256, 256>>>(
        (const float4*)Wq, (const float4*)Wk, (const float4*)Wv, (const float4*)Wp,
        (__half2*)wh, (__half2*)wl);

    const float QSCALE = 0.125f * 1.44269504088896f;   // 1/sqrt(64) * log2(e)

    dim3 qkv_grid(3*C_/128, NTOK/128);   // (24, 32)
    gemm_hmma<1><<<qkv_grid, 256, GEMM_SMEM>>>(
        xh, xl, wh, wl, bq, bk, bv, nullptr,
        qh, ql, kh, kl, vh, vl, QSCALE);

    attn_tc<<<dim3(T_/128, B_*H_), 128, AT_SMEM>>>();   // writes y hi/lo into xh/xl

    dim3 ggrid(C_/128, NTOK/128);        // (8, 32)
    gemm_hmma<0><<<ggrid, 256, GEMM_SMEM>>>(
        xh, xl, wh + 3*(size_t)C_*C_, wl + 3*(size_t)C_*C_, bp, nullptr, nullptr,
        out, nullptr, nullptr, nullptr, nullptr, nullptr, nullptr, 1.0f);
}

// round 9
// speedup vs baseline: 1.1242x; 1.1242x over previous
#include <cuda_runtime.h>
#include <cuda_fp16.h>
#include <math.h>
#include <stdint.h>

#define B_   2
#define T_   2048
#define C_   1024
#define H_   16
#define HD_  64
#define NTOK (B_*T_)   // 4096

// ---------------------------------------------------------------------------
// Scratch (__device__ globals; allocation-free rule)
// ---------------------------------------------------------------------------
__device__ __half g_qh[NTOK*C_], g_ql[NTOK*C_];
__device__ __half g_kh[NTOK*C_], g_kl[NTOK*C_];
__device__ __half g_vh[NTOK*C_], g_vl[NTOK*C_];
__device__ __half g_xh[NTOK*C_], g_xl[NTOK*C_];   // x hi/lo, later y hi/lo
__device__ __half g_wh[4*C_*C_], g_wl[4*C_*C_];   // Wq|Wk|Wv|Wp hi/lo

// ---------------------------------------------------------------------------
// PTX helpers (sm_80-baseline only — harness compiles for sm_103 w/o 'a')
// ---------------------------------------------------------------------------
__device__ __forceinline__ uint32_t smem_u32(const void* p) {
    uint32_t a;
    asm("{ .reg .u64 t; cvta.to.shared.u64 t, %1; cvt.u32.u64 %0, t; }"
        : "=r"(a) : "l"(p));
    return a;
}
__device__ __forceinline__ void cp16(uint32_t dst, const void* src) {
    asm volatile("cp.async.ca.shared.global [%0], [%1], 16;" :: "r"(dst), "l"(src));
}
#define CP_COMMIT()  asm volatile("cp.async.commit_group;" ::: "memory")
#define CP_WAIT(N)   asm volatile("cp.async.wait_group " #N ";" ::: "memory")

#define LDMX4(r, addr) \
    asm volatile("ldmatrix.sync.aligned.m8n8.x4.shared.b16 {%0,%1,%2,%3}, [%4];" \
        : "=r"((r)[0]), "=r"((r)[1]), "=r"((r)[2]), "=r"((r)[3]) : "r"(addr))
#define LDMX4T(r, addr) \
    asm volatile("ldmatrix.sync.aligned.m8n8.x4.trans.shared.b16 {%0,%1,%2,%3}, [%4];" \
        : "=r"((r)[0]), "=r"((r)[1]), "=r"((r)[2]), "=r"((r)[3]) : "r"(addr))

#define MMA16816(d, a, b) \
    asm volatile("mma.sync.aligned.m16n8k16.row.col.f32.f16.f16.f32 " \
        "{%0,%1,%2,%3}, {%4,%5,%6,%7}, {%8,%9}, {%0,%1,%2,%3};" \
        : "+f"((d)[0]), "+f"((d)[1]), "+f"((d)[2]), "+f"((d)[3]) \
        : "r"((a)[0]), "r"((a)[1]), "r"((a)[2]), "r"((a)[3]), \
          "r"((b)[0]), "r"((b)[1]))

__device__ __forceinline__ float ex2(float x) {
    float r;
    asm("ex2.approx.ftz.f32 %0, %1;" : "=f"(r) : "f"(x));
    return r;
}
__device__ __forceinline__ uint32_t packh2(float a, float b) {
    __half2 h = __floats2half2_rn(a, b);
    return *reinterpret_cast<uint32_t*>(&h);
}

// ---------------------------------------------------------------------------
// fp32 -> (hi, lo) fp16 split conversions
// ---------------------------------------------------------------------------
__global__ void __launch_bounds__(256)
cvt_split(const float4* __restrict__ src, __half2* __restrict__ hi,
          __half2* __restrict__ lo, int n4)
{
    int i = blockIdx.x * blockDim.x + threadIdx.x;
    if (i >= n4) return;
    float4 f = src[i];
    __half2 h01 = __floats2half2_rn(f.x, f.y);
    __half2 h23 = __floats2half2_rn(f.z, f.w);
    float2 b01 = __half22float2(h01);
    float2 b23 = __half22float2(h23);
    hi[2*i]   = h01;  hi[2*i+1] = h23;
    lo[2*i]   = __floats2half2_rn(f.x - b01.x, f.y - b01.y);
    lo[2*i+1] = __floats2half2_rn(f.z - b23.x, f.w - b23.y);
}

__global__ void __launch_bounds__(256)
cvt_split_w4(const float4* __restrict__ s0, const float4* __restrict__ s1,
             const float4* __restrict__ s2, const float4* __restrict__ s3,
             __half2* __restrict__ hi, __half2* __restrict__ lo)
{
    const int NW4 = C_ * C_ / 4;   // 262144 = 2^18
    int i = blockIdx.x * blockDim.x + threadIdx.x;
    if (i >= 4 * NW4) return;
    int mid = i >> 18;
    int off = i & (NW4 - 1);
    const float4* src = (mid == 0) ? s0 : (mid == 1) ? s1 : (mid == 2) ? s2 : s3;
    float4 f = src[off];
    __half2 h01 = __floats2half2_rn(f.x, f.y);
    __half2 h23 = __floats2half2_rn(f.z, f.w);
    float2 b01 = __half22float2(h01);
    float2 b23 = __half22float2(h23);
    hi[2*i]   = h01;  hi[2*i+1] = h23;
    lo[2*i]   = __floats2half2_rn(f.x - b01.x, f.y - b01.y);
    lo[2*i+1] = __floats2half2_rn(f.z - b23.x, f.w - b23.y);
}

// ---------------------------------------------------------------------------
// HMMA GEMM, split-fp16 3-term. CTA tile 128x128, BK=64, 2-stage cp.async.
// MODE 0: fp32 out [m][n].  MODE 1: merged QKV (N=3072), head-split hi/lo out.
// ---------------------------------------------------------------------------
#define GEMM_SMEM (2*65536)

__device__ __forceinline__ void load_stage(
    uint32_t sb,
    const __half* __restrict__ Ah, const __half* __restrict__ Al,
    const __half* __restrict__ Bh, const __half* __restrict__ Bl,
    int m0, int n0, int k0, int tid)
{
    #pragma unroll
    for (int i = 0; i < 4; i++) {
        int idx = tid + i * 256;
        int r = idx >> 3, u = idx & 7;
        uint32_t doff = r * 128 + ((u ^ (r & 7)) << 4);
        size_t aoff = (size_t)(m0 + r) * C_ + k0 + u * 8;
        size_t boff = (size_t)(n0 + r) * C_ + k0 + u * 8;
        cp16(sb +         doff, Ah + aoff);
        cp16(sb + 16384 + doff, Al + aoff);
        cp16(sb + 32768 + doff, Bh + boff);
        cp16(sb + 49152 + doff, Bl + boff);
    }
}

template<int MODE>
__global__ void __launch_bounds__(256)
gemm_hmma(const __half* __restrict__ Ah, const __half* __restrict__ Al,
          const __half* __restrict__ Bh, const __half* __restrict__ Bl,
          const float* __restrict__ b0, const float* __restrict__ b1,
          const float* __restrict__ b2,
          float* __restrict__ outf,
          __half* __restrict__ o0h, __half* __restrict__ o0l,
          __half* __restrict__ o1h, __half* __restrict__ o1l,
          __half* __restrict__ o2h, __half* __restrict__ o2l,
          float scale0)
{
    extern __shared__ __align__(1024) char smem[];
    uint32_t sbase = smem_u32(smem);
    const int tid  = threadIdx.x;
    const int lane = tid & 31;
    const int warp = tid >> 5;
    const int wm   = warp >> 2;
    const int wn   = warp & 3;
    const int m0   = blockIdx.y * 128;
    const int n0   = blockIdx.x * 128;

    float acc[4][4][4];
    #pragma unroll
    for (int i = 0; i < 4; i++)
        #pragma unroll
        for (int j = 0; j < 4; j++)
            #pragma unroll
            for (int k = 0; k < 4; k++) acc[i][j][k] = 0.f;

    load_stage(sbase, Ah, Al, Bh, Bl, m0, n0, 0, tid);
    CP_COMMIT();

    for (int kt = 0; kt < 16; kt++) {
        if (kt + 1 < 16) {
            load_stage(sbase + ((kt + 1) & 1) * 65536, Ah, Al, Bh, Bl,
                       m0, n0, (kt + 1) * 64, tid);
            CP_COMMIT();
            CP_WAIT(1);
        } else {
            CP_WAIT(0);
        }
        __syncthreads();

        uint32_t sb = sbase + (kt & 1) * 65536;

        #pragma unroll
        for (int ks = 0; ks < 4; ks++) {
            uint32_t ah[4][4], al[4][4];
            {
                int arow = wm * 64 + (lane & 15);
                int aku  = ks * 2 + (lane >> 4);
                #pragma unroll
                for (int mi = 0; mi < 4; mi++) {
                    int r = arow + mi * 16;
                    uint32_t addr = sb + r * 128 + ((aku ^ (r & 7)) << 4);
                    LDMX4(ah[mi], addr);
                    LDMX4(al[mi], addr + 16384);
                }
            }
            uint32_t bhf[4][2], blf[4][2];
            {
                int brow0 = wn * 32 + ((lane >> 4) << 3) + (lane & 7);
                int bku   = ks * 2 + ((lane >> 3) & 1);
                #pragma unroll
                for (int nj2 = 0; nj2 < 2; nj2++) {
                    int r = brow0 + nj2 * 16;
                    uint32_t addr = sb + 32768 + r * 128 + ((bku ^ (r & 7)) << 4);
                    uint32_t t[4];
                    LDMX4(t, addr);
                    bhf[2*nj2][0] = t[0]; bhf[2*nj2][1] = t[1];
                    bhf[2*nj2+1][0] = t[2]; bhf[2*nj2+1][1] = t[3];
                    LDMX4(t, addr + 16384);
                    blf[2*nj2][0] = t[0]; blf[2*nj2][1] = t[1];
                    blf[2*nj2+1][0] = t[2]; blf[2*nj2+1][1] = t[3];
                }
            }
            #pragma unroll
            for (int mi = 0; mi < 4; mi++)
                #pragma unroll
                for (int nj = 0; nj < 4; nj++) {
                    MMA16816(acc[mi][nj], ah[mi], bhf[nj]);
                    MMA16816(acc[mi][nj], al[mi], bhf[nj]);
                    MMA16816(acc[mi][nj], ah[mi], blf[nj]);
                }
        }
        __syncthreads();
    }

    const int r0 = lane >> 2;
    const int c0 = (lane & 3) * 2;

    const float* bias;
    __half *oh, *ol;
    float scale = 1.0f;
    if (MODE == 1) {
        int mid = n0 >> 10;
        bias = (mid == 0) ? b0 : (mid == 1) ? b1 : b2;
        oh   = (mid == 0) ? o0h : (mid == 1) ? o1h : o2h;
        ol   = (mid == 0) ? o0l : (mid == 1) ? o1l : o2l;
        if (mid == 0) scale = scale0;
    } else {
        bias = b0;
    }

    #pragma unroll
    for (int mi = 0; mi < 4; mi++) {
        #pragma unroll
        for (int nj = 0; nj < 4; nj++) {
            int nl = (n0 & 1023) + wn * 32 + nj * 8 + c0;
            float2 bv = *(const float2*)(bias + nl);
            #pragma unroll
            for (int h2 = 0; h2 < 2; h2++) {
                int m = m0 + wm * 64 + mi * 16 + r0 + h2 * 8;
                float v0 = acc[mi][nj][h2*2+0] + bv.x;
                float v1 = acc[mi][nj][h2*2+1] + bv.y;
                if (MODE == 0) {
                    float2 o = {v0, v1};
                    *(float2*)(outf + (size_t)m * C_ + nl) = o;
                } else {
                    v0 *= scale; v1 *= scale;
                    __half2 hh = __floats2half2_rn(v0, v1);
                    float2 hf = __half22float2(hh);
                    __half2 ll = __floats2half2_rn(v0 - hf.x, v1 - hf.y);
                    int b = m >> 11, t = m & (T_ - 1);
                    int h = nl >> 6, d = nl & 63;
                    size_t idx = (((size_t)(b * H_ + h)) * T_ + t) * HD_ + d;
                    *(__half2*)(oh + idx) = hh;
                    *(__half2*)(ol + idx) = ll;
                }
            }
        }
    }
}

// ---------------------------------------------------------------------------
// Tensor-core flash attention v5: 4-warp CTAs, 64 q-rows, 64-key blocks.
// 2-term splits: S = Qh*(Kh+Kl), O += Ph*(Vh+Vl)  (drop Ql, Pl terms —
// their contributions are incoherent 2^-11 rounding noise).
// smem 72 KB: Qh 8K | 2 stages x (Kh,Kl,Vh,Vl 8K each) -> 3 CTAs/SM.
// ---------------------------------------------------------------------------
#define AT_SMEM (8192 + 2*32768)

__global__ void __launch_bounds__(128, 3) attn_tc()
{
    extern __shared__ __align__(1024) char smem[];
    uint32_t sb = smem_u32(smem);
    const int tid  = threadIdx.x;
    const int lane = tid & 31;
    const int warp = tid >> 5;                              // 0..3
    const int qt   = (int)gridDim.x - 1 - (int)blockIdx.x;  // heavy first
    const int bh   = blockIdx.y;
    const int nkb  = qt + 1;                                // 64-key blocks

    const __half* qhp = g_qh + ((size_t)bh * T_ + qt * 64) * HD_;
    const __half* khp = g_kh + (size_t)bh * T_ * HD_;
    const __half* klp = g_kl + (size_t)bh * T_ * HD_;
    const __half* vhp = g_vh + (size_t)bh * T_ * HD_;
    const __half* vlp = g_vl + (size_t)bh * T_ * HD_;

    // ---- load Qh: 64 rows x 8 units = 512 cp16 ----
    #pragma unroll
    for (int i = 0; i < 4; i++) {
        int idx = tid + i * 128;               // 0..511
        int r = idx >> 3, u = idx & 7;
        cp16(sb + r * 128 + ((u ^ (r & 7)) << 4), qhp + (size_t)r * HD_ + u * 8);
    }
    CP_COMMIT();

    // ---- K/V stage loader: Kh,Kl,Vh,Vl @ 8 KB each = 2048 cp16 ----
    auto load_kv = [&](int stage, int kb) {
        uint32_t st = sb + 8192 + stage * 32768;
        #pragma unroll
        for (int i = 0; i < 16; i++) {
            int idx = tid + i * 128;           // 0..2047
            int a = idx >> 9;                  // 0:Kh 1:Kl 2:Vh 3:Vl
            int w = idx & 511;
            int r = w >> 3, u = w & 7;
            const __half* src;
            switch (a) {
                case 0: src = khp; break;
                case 1: src = klp; break;
                case 2: src = vhp; break;
                default: src = vlp; break;
            }
            src += ((size_t)(kb * 64 + r)) * HD_ + u * 8;
            cp16(st + a * 8192 + r * 128 + ((u ^ (r & 7)) << 4), src);
        }
    };
    load_kv(0, 0);
    CP_COMMIT();

    // ---- wait for Q, load Q fragments (kept resident: 16 regs) ----
    CP_WAIT(1);
    __syncthreads();
    uint32_t qfh[4][4];
    {
        int arow = warp * 16 + (lane & 15);
        #pragma unroll
        for (int ks = 0; ks < 4; ks++) {
            int u = ks * 2 + (lane >> 4);
            LDMX4(qfh[ks], sb + arow * 128 + ((u ^ (arow & 7)) << 4));
        }
    }

    float o[8][4];
    #pragma unroll
    for (int j = 0; j < 8; j++)
        #pragma unroll
        for (int e = 0; e < 4; e++) o[j][e] = 0.f;
    float mrow[2] = {-1e30f, -1e30f};
    float lrow[2] = {0.f, 0.f};

    for (int kb = 0; kb < nkb; kb++) {
        if (kb + 1 < nkb) { load_kv((kb + 1) & 1, kb + 1); CP_COMMIT(); CP_WAIT(1); }
        else              { CP_WAIT(0); }
        __syncthreads();

        const bool diag = (kb == nkb - 1);
        uint32_t st = sb + 8192 + (kb & 1) * 32768;    // Kh (Kl at +8192)
        uint32_t sv = st + 16384;                      // Vh (Vl at +8192)

        // ---- S = Qh (Kh + Kl)^T; diag: skip key groups g > warp ----
        float s[8][4];
        #pragma unroll
        for (int j = 0; j < 8; j++)
            #pragma unroll
            for (int e = 0; e < 4; e++) s[j][e] = 0.f;

        #pragma unroll
        for (int ks = 0; ks < 4; ks++) {
            #pragma unroll
            for (int g = 0; g < 4; g++) {
                if (!diag || g <= warp) {
                    int brow = g * 16 + ((lane >> 4) << 3) + (lane & 7);
                    int bku  = ks * 2 + ((lane >> 3) & 1);
                    uint32_t addr = st + brow * 128 + ((bku ^ (brow & 7)) << 4);
                    uint32_t kh4[4], kl4[4];
                    LDMX4(kh4, addr);
                    LDMX4(kl4, addr + 8192);
                    MMA16816(s[2*g],   qfh[ks], kh4);
                    MMA16816(s[2*g],   qfh[ks], kl4);
                    MMA16816(s[2*g+1], qfh[ks], kh4 + 2);
                    MMA16816(s[2*g+1], qfh[ks], kl4 + 2);
                }
            }
        }

        if (diag) {
            int rbase = warp * 16 + (lane >> 2);
            int cbase = 2 * (lane & 3);
            #pragma unroll
            for (int j = 0; j < 8; j++) {
                int c = 8 * j + cbase;
                if (c     > rbase)     s[j][0] = -1e30f;
                if (c + 1 > rbase)     s[j][1] = -1e30f;
                if (c     > rbase + 8) s[j][2] = -1e30f;
                if (c + 1 > rbase + 8) s[j][3] = -1e30f;
            }
        }

        // ---- online softmax (base-2; scale folded into Q) ----
        float mloc0 = -1e30f, mloc1 = -1e30f;
        #pragma unroll
        for (int j = 0; j < 8; j++) {
            mloc0 = fmaxf(mloc0, fmaxf(s[j][0], s[j][1]));
            mloc1 = fmaxf(mloc1, fmaxf(s[j][2], s[j][3]));
        }
        #pragma unroll
        for (int off = 1; off < 4; off <<= 1) {
            mloc0 = fmaxf(mloc0, __shfl_xor_sync(0xffffffffu, mloc0, off));
            mloc1 = fmaxf(mloc1, __shfl_xor_sync(0xffffffffu, mloc1, off));
        }
        float mn0 = fmaxf(mrow[0], mloc0);
        float mn1 = fmaxf(mrow[1], mloc1);
        float cr0 = ex2(mrow[0] - mn0);
        float cr1 = ex2(mrow[1] - mn1);
        mrow[0] = mn0; mrow[1] = mn1;

        float sum0 = 0.f, sum1 = 0.f;
        #pragma unroll
        for (int j = 0; j < 8; j++) {
            s[j][0] = ex2(s[j][0] - mn0); sum0 += s[j][0];
            s[j][1] = ex2(s[j][1] - mn0); sum0 += s[j][1];
            s[j][2] = ex2(s[j][2] - mn1); sum1 += s[j][2];
            s[j][3] = ex2(s[j][3] - mn1); sum1 += s[j][3];
        }
        #pragma unroll
        for (int off = 1; off < 4; off <<= 1) {
            sum0 += __shfl_xor_sync(0xffffffffu, sum0, off);
            sum1 += __shfl_xor_sync(0xffffffffu, sum1, off);
        }
        lrow[0] = lrow[0] * cr0 + sum0;
        lrow[1] = lrow[1] * cr1 + sum1;

        #pragma unroll
        for (int j = 0; j < 8; j++) {
            o[j][0] *= cr0; o[j][1] *= cr0;
            o[j][2] *= cr1; o[j][3] *= cr1;
        }

        // ---- O += Ph (Vh + Vl); diag: skip key chunks kk > warp ----
        #pragma unroll
        for (int kk = 0; kk < 4; kk++) {
            if (!diag || kk <= warp) {
                uint32_t ph[4];
                ph[0] = packh2(s[2*kk][0],   s[2*kk][1]);
                ph[1] = packh2(s[2*kk][2],   s[2*kk][3]);
                ph[2] = packh2(s[2*kk+1][0], s[2*kk+1][1]);
                ph[3] = packh2(s[2*kk+1][2], s[2*kk+1][3]);
                int vrow = kk * 16 + ((lane >> 3) & 1) * 8 + (lane & 7);
                #pragma unroll
                for (int g = 0; g < 4; g++) {
                    int vu = 2 * g + (lane >> 4);
                    uint32_t addr = sv + vrow * 128 + ((vu ^ (vrow & 7)) << 4);
                    uint32_t vh4[4], vl4[4];
                    LDMX4T(vh4, addr);
                    LDMX4T(vl4, addr + 8192);
                    MMA16816(o[2*g],   ph, vh4);
                    MMA16816(o[2*g],   ph, vl4);
                    MMA16816(o[2*g+1], ph, vh4 + 2);
                    MMA16816(o[2*g+1], ph, vl4 + 2);
                }
            }
        }
        __syncthreads();   // all warps done with stage kb before kb+2 overwrite
    }

    // ---- epilogue: y = O / l -> hi/lo halves into out-proj input buffers ----
    float inv0 = 1.0f / lrow[0];
    float inv1 = 1.0f / lrow[1];
    int b = bh >> 4;
    int h = bh & 15;
    int t0 = qt * 64 + warp * 16 + (lane >> 2);
    int d0 = 2 * (lane & 3);
    #pragma unroll
    for (int j = 0; j < 8; j++) {
        int d = 8 * j + d0;
        {
            float y0 = o[j][0] * inv0, y1 = o[j][1] * inv0;
            __half2 hh = __floats2half2_rn(y0, y1);
            float2 hf = __half22float2(hh);
            __half2 ll = __floats2half2_rn(y0 - hf.x, y1 - hf.y);
            size_t idx = ((size_t)(b * T_ + t0)) * C_ + h * HD_ + d;
            *(__half2*)(g_xh + idx) = hh;
            *(__half2*)(g_xl + idx) = ll;
        }
        {
            float y0 = o[j][2] * inv1, y1 = o[j][3] * inv1;
            __half2 hh = __floats2half2_rn(y0, y1);
            float2 hf = __half22float2(hh);
            __half2 ll = __floats2half2_rn(y0 - hf.x, y1 - hf.y);
            size_t idx = ((size_t)(b * T_ + t0 + 8)) * C_ + h * HD_ + d;
            *(__half2*)(g_xh + idx) = hh;
            *(__half2*)(g_xl + idx) = ll;
        }
    }
}

// ---------------------------------------------------------------------------
extern "C" void kernel_launch(void* const* d_in, const int* in_sizes, int n_in,
                              void* d_out, int out_size)
{
    const float* x  = (const float*)d_in[0];
    const float* Wq = (const float*)d_in[1];
    const float* bq = (const float*)d_in[2];
    const float* Wk = (const float*)d_in[3];
    const float* bk = (const float*)d_in[4];
    const float* Wv = (const float*)d_in[5];
    const float* bv = (const float*)d_in[6];
    const float* Wp = (const float*)d_in[7];
    const float* bp = (const float*)d_in[8];
    float* out = (float*)d_out;

    __half *qh, *ql, *kh, *kl, *vh, *vl, *xh, *xl, *wh, *wl;
    cudaGetSymbolAddress((void**)&qh, g_qh);
    cudaGetSymbolAddress((void**)&ql, g_ql);
    cudaGetSymbolAddress((void**)&kh, g_kh);
    cudaGetSymbolAddress((void**)&kl, g_kl);
    cudaGetSymbolAddress((void**)&vh, g_vh);
    cudaGetSymbolAddress((void**)&vl, g_vl);
    cudaGetSymbolAddress((void**)&xh, g_xh);
    cudaGetSymbolAddress((void**)&xl, g_xl);
    cudaGetSymbolAddress((void**)&wh, g_wh);
    cudaGetSymbolAddress((void**)&wl, g_wl);

    cudaFuncSetAttribute(gemm_hmma<0>, cudaFuncAttributeMaxDynamicSharedMemorySize, GEMM_SMEM);
    cudaFuncSetAttribute(gemm_hmma<1>, cudaFuncAttributeMaxDynamicSharedMemorySize, GEMM_SMEM);
    cudaFuncSetAttribute(attn_tc, cudaFuncAttributeMaxDynamicSharedMemorySize, AT_SMEM);

    const int NX4 = NTOK * C_ / 4;     // 1M
    const int NW4 = C_ * C_ / 4;       // 256K
    cvt_split<<<(NX4 + 255)/256, 256>>>((const float4*)x, (__half2*)xh, (__half2*)xl, NX4);
    cvt_split_w4<<<(4*NW4 + 255)/256, 256>>>(
        (const float4*)Wq, (const float4*)Wk, (const float4*)Wv, (const float4*)Wp,
        (__half2*)wh, (__half2*)wl);

    const float QSCALE = 0.125f * 1.44269504088896f;   // 1/sqrt(64) * log2(e)

    dim3 qkv_grid(3*C_/128, NTOK/128);   // (24, 32)
    gemm_hmma<1><<<qkv_grid, 256, GEMM_SMEM>>>(
        xh, xl, wh, wl, bq, bk, bv, nullptr,
        qh, ql, kh, kl, vh, vl, QSCALE);

    attn_tc<<<dim3(T_/64, B_*H_), 128, AT_SMEM>>>();   // writes y hi/lo into xh/xl

    dim3 ggrid(C_/128, NTOK/128);        // (8, 32)
    gemm_hmma<0><<<ggrid, 256, GEMM_SMEM>>>(
        xh, xl, wh + 3*(size_t)C_*C_, wl + 3*(size_t)C_*C_, bp, nullptr, nullptr,
        out, nullptr, nullptr, nullptr, nullptr, nullptr, nullptr, 1.0f);
}

// round 10
// speedup vs baseline: 1.1248x; 1.0006x over previous
#include <cuda_runtime.h>
#include <cuda_fp16.h>
#include <math.h>
#include <stdint.h>

#define B_   2
#define T_   2048
#define C_   1024
#define H_   16
#define HD_  64
#define NTOK (B_*T_)   // 4096

// ---------------------------------------------------------------------------
// Scratch (__device__ globals; allocation-free rule)
// ---------------------------------------------------------------------------
__device__ __half g_qh[NTOK*C_], g_ql[NTOK*C_];
__device__ __half g_kh[NTOK*C_], g_kl[NTOK*C_];
__device__ __half g_vh[NTOK*C_], g_vl[NTOK*C_];
__device__ __half g_xh[NTOK*C_], g_xl[NTOK*C_];   // x hi/lo, later y hi/lo
__device__ __half g_wh[4*C_*C_], g_wl[4*C_*C_];   // Wq|Wk|Wv|Wp hi/lo

// ---------------------------------------------------------------------------
// PTX helpers (sm_80-baseline only — harness compiles for sm_103 w/o 'a')
// ---------------------------------------------------------------------------
__device__ __forceinline__ uint32_t smem_u32(const void* p) {
    uint32_t a;
    asm("{ .reg .u64 t; cvta.to.shared.u64 t, %1; cvt.u32.u64 %0, t; }"
        : "=r"(a) : "l"(p));
    return a;
}
__device__ __forceinline__ void cp16(uint32_t dst, const void* src) {
    asm volatile("cp.async.ca.shared.global [%0], [%1], 16;" :: "r"(dst), "l"(src));
}
#define CP_COMMIT()  asm volatile("cp.async.commit_group;" ::: "memory")
#define CP_WAIT(N)   asm volatile("cp.async.wait_group " #N ";" ::: "memory")

#define LDMX4(r, addr) \
    asm volatile("ldmatrix.sync.aligned.m8n8.x4.shared.b16 {%0,%1,%2,%3}, [%4];" \
        : "=r"((r)[0]), "=r"((r)[1]), "=r"((r)[2]), "=r"((r)[3]) : "r"(addr))
#define LDMX4T(r, addr) \
    asm volatile("ldmatrix.sync.aligned.m8n8.x4.trans.shared.b16 {%0,%1,%2,%3}, [%4];" \
        : "=r"((r)[0]), "=r"((r)[1]), "=r"((r)[2]), "=r"((r)[3]) : "r"(addr))

#define MMA16816(d, a, b) \
    asm volatile("mma.sync.aligned.m16n8k16.row.col.f32.f16.f16.f32 " \
        "{%0,%1,%2,%3}, {%4,%5,%6,%7}, {%8,%9}, {%0,%1,%2,%3};" \
        : "+f"((d)[0]), "+f"((d)[1]), "+f"((d)[2]), "+f"((d)[3]) \
        : "r"((a)[0]), "r"((a)[1]), "r"((a)[2]), "r"((a)[3]), \
          "r"((b)[0]), "r"((b)[1]))

__device__ __forceinline__ float ex2(float x) {
    float r;
    asm("ex2.approx.ftz.f32 %0, %1;" : "=f"(r) : "f"(x));
    return r;
}
__device__ __forceinline__ uint32_t packh2(float a, float b) {
    __half2 h = __floats2half2_rn(a, b);
    return *reinterpret_cast<uint32_t*>(&h);
}

// ---------------------------------------------------------------------------
// fp32 -> (hi, lo) fp16 split conversion — x and all 4 weights in ONE launch
// ---------------------------------------------------------------------------
__global__ void __launch_bounds__(256)
cvt_split_all(const float4* __restrict__ x,
              const float4* __restrict__ w0, const float4* __restrict__ w1,
              const float4* __restrict__ w2, const float4* __restrict__ w3,
              __half2* __restrict__ xhi, __half2* __restrict__ xlo,
              __half2* __restrict__ whi, __half2* __restrict__ wlo)
{
    const int NX4 = NTOK * C_ / 4;   // 1048576
    const int NW4 = C_ * C_ / 4;     // 262144 = 2^18
    int i = blockIdx.x * blockDim.x + threadIdx.x;
    const float4* src;
    __half2 *hi, *lo;
    if (i < NX4) {
        src = x + i; hi = xhi + 2*i; lo = xlo + 2*i;
    } else {
        int j = i - NX4;
        if (j >= 4 * NW4) return;
        int mid = j >> 18;
        int off = j & (NW4 - 1);
        src = ((mid == 0) ? w0 : (mid == 1) ? w1 : (mid == 2) ? w2 : w3) + off;
        hi = whi + 2*j; lo = wlo + 2*j;
    }
    float4 f = *src;
    __half2 h01 = __floats2half2_rn(f.x, f.y);
    __half2 h23 = __floats2half2_rn(f.z, f.w);
    float2 b01 = __half22float2(h01);
    float2 b23 = __half22float2(h23);
    hi[0] = h01;  hi[1] = h23;
    lo[0] = __floats2half2_rn(f.x - b01.x, f.y - b01.y);
    lo[1] = __floats2half2_rn(f.z - b23.x, f.w - b23.y);
}

// y (attn output) conversion
__global__ void __launch_bounds__(256)
cvt_split(const float4* __restrict__ src, __half2* __restrict__ hi,
          __half2* __restrict__ lo, int n4)
{
    int i = blockIdx.x * blockDim.x + threadIdx.x;
    if (i >= n4) return;
    float4 f = src[i];
    __half2 h01 = __floats2half2_rn(f.x, f.y);
    __half2 h23 = __floats2half2_rn(f.z, f.w);
    float2 b01 = __half22float2(h01);
    float2 b23 = __half22float2(h23);
    hi[2*i]   = h01;  hi[2*i+1] = h23;
    lo[2*i]   = __floats2half2_rn(f.x - b01.x, f.y - b01.y);
    lo[2*i+1] = __floats2half2_rn(f.z - b23.x, f.w - b23.y);
}

// ---------------------------------------------------------------------------
// HMMA GEMM, split-fp16 3-term. CTA tile 128x128, BK=64, 2-stage cp.async.
// MODE 0: fp32 out [m][n].  MODE 1: merged QKV (N=3072), head-split hi/lo out.
// ---------------------------------------------------------------------------
#define GEMM_SMEM (2*65536)

__device__ __forceinline__ void load_stage(
    uint32_t sb,
    const __half* __restrict__ Ah, const __half* __restrict__ Al,
    const __half* __restrict__ Bh, const __half* __restrict__ Bl,
    int m0, int n0, int k0, int tid)
{
    #pragma unroll
    for (int i = 0; i < 4; i++) {
        int idx = tid + i * 256;
        int r = idx >> 3, u = idx & 7;
        uint32_t doff = r * 128 + ((u ^ (r & 7)) << 4);
        size_t aoff = (size_t)(m0 + r) * C_ + k0 + u * 8;
        size_t boff = (size_t)(n0 + r) * C_ + k0 + u * 8;
        cp16(sb +         doff, Ah + aoff);
        cp16(sb + 16384 + doff, Al + aoff);
        cp16(sb + 32768 + doff, Bh + boff);
        cp16(sb + 49152 + doff, Bl + boff);
    }
}

template<int MODE>
__global__ void __launch_bounds__(256)
gemm_hmma(const __half* __restrict__ Ah, const __half* __restrict__ Al,
          const __half* __restrict__ Bh, const __half* __restrict__ Bl,
          const float* __restrict__ b0, const float* __restrict__ b1,
          const float* __restrict__ b2,
          float* __restrict__ outf,
          __half* __restrict__ o0h, __half* __restrict__ o0l,
          __half* __restrict__ o1h, __half* __restrict__ o1l,
          __half* __restrict__ o2h, __half* __restrict__ o2l,
          float scale0)
{
    extern __shared__ __align__(1024) char smem[];
    uint32_t sbase = smem_u32(smem);
    const int tid  = threadIdx.x;
    const int lane = tid & 31;
    const int warp = tid >> 5;
    const int wm   = warp >> 2;
    const int wn   = warp & 3;
    const int m0   = blockIdx.y * 128;
    const int n0   = blockIdx.x * 128;

    float acc[4][4][4];
    #pragma unroll
    for (int i = 0; i < 4; i++)
        #pragma unroll
        for (int j = 0; j < 4; j++)
            #pragma unroll
            for (int k = 0; k < 4; k++) acc[i][j][k] = 0.f;

    load_stage(sbase, Ah, Al, Bh, Bl, m0, n0, 0, tid);
    CP_COMMIT();

    for (int kt = 0; kt < 16; kt++) {
        if (kt + 1 < 16) {
            load_stage(sbase + ((kt + 1) & 1) * 65536, Ah, Al, Bh, Bl,
                       m0, n0, (kt + 1) * 64, tid);
            CP_COMMIT();
            CP_WAIT(1);
        } else {
            CP_WAIT(0);
        }
        __syncthreads();

        uint32_t sb = sbase + (kt & 1) * 65536;

        #pragma unroll
        for (int ks = 0; ks < 4; ks++) {
            uint32_t ah[4][4], al[4][4];
            {
                int arow = wm * 64 + (lane & 15);
                int aku  = ks * 2 + (lane >> 4);
                #pragma unroll
                for (int mi = 0; mi < 4; mi++) {
                    int r = arow + mi * 16;
                    uint32_t addr = sb + r * 128 + ((aku ^ (r & 7)) << 4);
                    LDMX4(ah[mi], addr);
                    LDMX4(al[mi], addr + 16384);
                }
            }
            uint32_t bhf[4][2], blf[4][2];
            {
                int brow0 = wn * 32 + ((lane >> 4) << 3) + (lane & 7);
                int bku   = ks * 2 + ((lane >> 3) & 1);
                #pragma unroll
                for (int nj2 = 0; nj2 < 2; nj2++) {
                    int r = brow0 + nj2 * 16;
                    uint32_t addr = sb + 32768 + r * 128 + ((bku ^ (r & 7)) << 4);
                    uint32_t t[4];
                    LDMX4(t, addr);
                    bhf[2*nj2][0] = t[0]; bhf[2*nj2][1] = t[1];
                    bhf[2*nj2+1][0] = t[2]; bhf[2*nj2+1][1] = t[3];
                    LDMX4(t, addr + 16384);
                    blf[2*nj2][0] = t[0]; blf[2*nj2][1] = t[1];
                    blf[2*nj2+1][0] = t[2]; blf[2*nj2+1][1] = t[3];
                }
            }
            #pragma unroll
            for (int mi = 0; mi < 4; mi++)
                #pragma unroll
                for (int nj = 0; nj < 4; nj++) {
                    MMA16816(acc[mi][nj], ah[mi], bhf[nj]);
                    MMA16816(acc[mi][nj], al[mi], bhf[nj]);
                    MMA16816(acc[mi][nj], ah[mi], blf[nj]);
                }
        }
        __syncthreads();
    }

    const int r0 = lane >> 2;
    const int c0 = (lane & 3) * 2;

    const float* bias;
    __half *oh, *ol;
    float scale = 1.0f;
    if (MODE == 1) {
        int mid = n0 >> 10;
        bias = (mid == 0) ? b0 : (mid == 1) ? b1 : b2;
        oh   = (mid == 0) ? o0h : (mid == 1) ? o1h : o2h;
        ol   = (mid == 0) ? o0l : (mid == 1) ? o1l : o2l;
        if (mid == 0) scale = scale0;
    } else {
        bias = b0;
    }

    #pragma unroll
    for (int mi = 0; mi < 4; mi++) {
        #pragma unroll
        for (int nj = 0; nj < 4; nj++) {
            int nl = (n0 & 1023) + wn * 32 + nj * 8 + c0;
            float2 bv = *(const float2*)(bias + nl);
            #pragma unroll
            for (int h2 = 0; h2 < 2; h2++) {
                int m = m0 + wm * 64 + mi * 16 + r0 + h2 * 8;
                float v0 = acc[mi][nj][h2*2+0] + bv.x;
                float v1 = acc[mi][nj][h2*2+1] + bv.y;
                if (MODE == 0) {
                    float2 o = {v0, v1};
                    *(float2*)(outf + (size_t)m * C_ + nl) = o;
                } else {
                    v0 *= scale; v1 *= scale;
                    __half2 hh = __floats2half2_rn(v0, v1);
                    float2 hf = __half22float2(hh);
                    __half2 ll = __floats2half2_rn(v0 - hf.x, v1 - hf.y);
                    int b = m >> 11, t = m & (T_ - 1);
                    int h = nl >> 6, d = nl & 63;
                    size_t idx = (((size_t)(b * H_ + h)) * T_ + t) * HD_ + d;
                    *(__half2*)(oh + idx) = hh;
                    *(__half2*)(ol + idx) = ll;
                }
            }
        }
    }
}

// ---------------------------------------------------------------------------
// Tensor-core flash attention v6: 4 warps x 32 q-rows = 128 q-rows per CTA,
// 64-key blocks, 2-term splits (S = Qh*(Kh+Kl), O += Ph*(Vh+Vl)).
// K/V LDSM amortized over 2 m-tiles -> 128 B smem per MMA (was 256).
// smem 80 KB: Qh 16K | 2 stages x (Kh,Kl,Vh,Vl 8K each) -> 2 CTAs/SM.
// ---------------------------------------------------------------------------
#define AT_SMEM (16384 + 2*32768)

__global__ void __launch_bounds__(128, 2) attn_tc()
{
    extern __shared__ __align__(1024) char smem[];
    uint32_t sb = smem_u32(smem);
    const int tid  = threadIdx.x;
    const int lane = tid & 31;
    const int warp = tid >> 5;                              // 0..3
    const int qt   = (int)gridDim.x - 1 - (int)blockIdx.x;  // heavy first (128-row tiles)
    const int bh   = blockIdx.y;
    const int nkb  = 2 * qt + 2;                            // 64-key blocks

    const __half* qhp = g_qh + ((size_t)bh * T_ + qt * 128) * HD_;
    const __half* khp = g_kh + (size_t)bh * T_ * HD_;
    const __half* klp = g_kl + (size_t)bh * T_ * HD_;
    const __half* vhp = g_vh + (size_t)bh * T_ * HD_;
    const __half* vlp = g_vl + (size_t)bh * T_ * HD_;

    // ---- load Qh: 128 rows x 8 units = 1024 cp16 ----
    #pragma unroll
    for (int i = 0; i < 8; i++) {
        int idx = tid + i * 128;               // 0..1023
        int r = idx >> 3, u = idx & 7;
        cp16(sb + r * 128 + ((u ^ (r & 7)) << 4), qhp + (size_t)r * HD_ + u * 8);
    }
    CP_COMMIT();

    // ---- K/V stage loader: Kh,Kl,Vh,Vl @ 8 KB each = 2048 cp16 ----
    auto load_kv = [&](int stage, int kb) {
        uint32_t st = sb + 16384 + stage * 32768;
        #pragma unroll
        for (int i = 0; i < 16; i++) {
            int idx = tid + i * 128;           // 0..2047
            int a = idx >> 9;                  // 0:Kh 1:Kl 2:Vh 3:Vl
            int w = idx & 511;
            int r = w >> 3, u = w & 7;
            const __half* src;
            switch (a) {
                case 0: src = khp; break;
                case 1: src = klp; break;
                case 2: src = vhp; break;
                default: src = vlp; break;
            }
            src += ((size_t)(kb * 64 + r)) * HD_ + u * 8;
            cp16(st + a * 8192 + r * 128 + ((u ^ (r & 7)) << 4), src);
        }
    };
    load_kv(0, 0);
    CP_COMMIT();

    // ---- wait for Q, load resident Q fragments (2 m-tiles x 4 ks = 32 regs)
    CP_WAIT(1);
    __syncthreads();
    uint32_t qfh[2][4][4];
    #pragma unroll
    for (int mi = 0; mi < 2; mi++) {
        int arow = warp * 32 + mi * 16 + (lane & 15);
        #pragma unroll
        for (int ks = 0; ks < 4; ks++) {
            int u = ks * 2 + (lane >> 4);
            LDMX4(qfh[mi][ks], sb + arow * 128 + ((u ^ (arow & 7)) << 4));
        }
    }

    float o[2][8][4];
    #pragma unroll
    for (int mi = 0; mi < 2; mi++)
        #pragma unroll
        for (int j = 0; j < 8; j++)
            #pragma unroll
            for (int e = 0; e < 4; e++) o[mi][j][e] = 0.f;
    float mrow[2][2] = {{-1e30f, -1e30f}, {-1e30f, -1e30f}};
    float lrow[2][2] = {{0.f, 0.f}, {0.f, 0.f}};

    for (int kb = 0; kb < nkb; kb++) {
        if (kb + 1 < nkb) { load_kv((kb + 1) & 1, kb + 1); CP_COMMIT(); CP_WAIT(1); }
        else              { CP_WAIT(0); }
        __syncthreads();

        const bool maskblk = (kb >= 2 * qt);          // last two blocks are partial
        const int  kloc    = (kb - 2 * qt) * 64;      // key offset rel. to q-tile base
        uint32_t st = sb + 16384 + (kb & 1) * 32768;  // Kh (Kl +8192)
        uint32_t sv = st + 16384;                     // Vh (Vl +8192)

        // ---- S = Qh (Kh + Kl)^T, 2 m-tiles per warp ----
        float s[2][8][4];
        #pragma unroll
        for (int mi = 0; mi < 2; mi++)
            #pragma unroll
            for (int j = 0; j < 8; j++)
                #pragma unroll
                for (int e = 0; e < 4; e++) s[mi][j][e] = 0.f;

        #pragma unroll
        for (int ks = 0; ks < 4; ks++) {
            #pragma unroll
            for (int g = 0; g < 4; g++) {
                if (!maskblk || kloc + 16 * g <= 32 * warp + 31) {
                    int brow = g * 16 + ((lane >> 4) << 3) + (lane & 7);
                    int bku  = ks * 2 + ((lane >> 3) & 1);
                    uint32_t addr = st + brow * 128 + ((bku ^ (brow & 7)) << 4);
                    uint32_t kh4[4], kl4[4];
                    LDMX4(kh4, addr);
                    LDMX4(kl4, addr + 8192);
                    #pragma unroll
                    for (int mi = 0; mi < 2; mi++) {
                        if (!maskblk || kloc + 16 * g <= 32 * warp + mi * 16 + 15) {
                            MMA16816(s[mi][2*g],   qfh[mi][ks], kh4);
                            MMA16816(s[mi][2*g],   qfh[mi][ks], kl4);
                            MMA16816(s[mi][2*g+1], qfh[mi][ks], kh4 + 2);
                            MMA16816(s[mi][2*g+1], qfh[mi][ks], kl4 + 2);
                        }
                    }
                }
            }
        }

        if (maskblk) {
            #pragma unroll
            for (int mi = 0; mi < 2; mi++) {
                int rbase = 32 * warp + 16 * mi + (lane >> 2);
                int cbase = kloc + 2 * (lane & 3);
                #pragma unroll
                for (int j = 0; j < 8; j++) {
                    int c = cbase + 8 * j;
                    if (c     > rbase)     s[mi][j][0] = -1e30f;
                    if (c + 1 > rbase)     s[mi][j][1] = -1e30f;
                    if (c     > rbase + 8) s[mi][j][2] = -1e30f;
                    if (c + 1 > rbase + 8) s[mi][j][3] = -1e30f;
                }
            }
        }

        // ---- online softmax (base-2; scale folded into Q) ----
        #pragma unroll
        for (int mi = 0; mi < 2; mi++) {
            float mloc0 = -1e30f, mloc1 = -1e30f;
            #pragma unroll
            for (int j = 0; j < 8; j++) {
                mloc0 = fmaxf(mloc0, fmaxf(s[mi][j][0], s[mi][j][1]));
                mloc1 = fmaxf(mloc1, fmaxf(s[mi][j][2], s[mi][j][3]));
            }
            #pragma unroll
            for (int off = 1; off < 4; off <<= 1) {
                mloc0 = fmaxf(mloc0, __shfl_xor_sync(0xffffffffu, mloc0, off));
                mloc1 = fmaxf(mloc1, __shfl_xor_sync(0xffffffffu, mloc1, off));
            }
            float mn0 = fmaxf(mrow[mi][0], mloc0);
            float mn1 = fmaxf(mrow[mi][1], mloc1);
            float cr0 = ex2(mrow[mi][0] - mn0);
            float cr1 = ex2(mrow[mi][1] - mn1);
            mrow[mi][0] = mn0; mrow[mi][1] = mn1;

            float sum0 = 0.f, sum1 = 0.f;
            #pragma unroll
            for (int j = 0; j < 8; j++) {
                s[mi][j][0] = ex2(s[mi][j][0] - mn0); sum0 += s[mi][j][0];
                s[mi][j][1] = ex2(s[mi][j][1] - mn0); sum0 += s[mi][j][1];
                s[mi][j][2] = ex2(s[mi][j][2] - mn1); sum1 += s[mi][j][2];
                s[mi][j][3] = ex2(s[mi][j][3] - mn1); sum1 += s[mi][j][3];
            }
            #pragma unroll
            for (int off = 1; off < 4; off <<= 1) {
                sum0 += __shfl_xor_sync(0xffffffffu, sum0, off);
                sum1 += __shfl_xor_sync(0xffffffffu, sum1, off);
            }
            lrow[mi][0] = lrow[mi][0] * cr0 + sum0;
            lrow[mi][1] = lrow[mi][1] * cr1 + sum1;

            #pragma unroll
            for (int j = 0; j < 8; j++) {
                o[mi][j][0] *= cr0; o[mi][j][1] *= cr0;
                o[mi][j][2] *= cr1; o[mi][j][3] *= cr1;
            }
        }

        // ---- O += Ph (Vh + Vl); per-(kk,mi) diag skip ----
        #pragma unroll
        for (int kk = 0; kk < 4; kk++) {
            if (!maskblk || kloc + 16 * kk <= 32 * warp + 31) {
                uint32_t ph[2][4];
                #pragma unroll
                for (int mi = 0; mi < 2; mi++) {
                    ph[mi][0] = packh2(s[mi][2*kk][0],   s[mi][2*kk][1]);
                    ph[mi][1] = packh2(s[mi][2*kk][2],   s[mi][2*kk][3]);
                    ph[mi][2] = packh2(s[mi][2*kk+1][0], s[mi][2*kk+1][1]);
                    ph[mi][3] = packh2(s[mi][2*kk+1][2], s[mi][2*kk+1][3]);
                }
                int vrow = kk * 16 + ((lane >> 3) & 1) * 8 + (lane & 7);
                #pragma unroll
                for (int g = 0; g < 4; g++) {
                    int vu = 2 * g + (lane >> 4);
                    uint32_t addr = sv + vrow * 128 + ((vu ^ (vrow & 7)) << 4);
                    uint32_t vh4[4], vl4[4];
                    LDMX4T(vh4, addr);
                    LDMX4T(vl4, addr + 8192);
                    #pragma unroll
                    for (int mi = 0; mi < 2; mi++) {
                        if (!maskblk || kloc + 16 * kk <= 32 * warp + mi * 16 + 15) {
                            MMA16816(o[mi][2*g],   ph[mi], vh4);
                            MMA16816(o[mi][2*g],   ph[mi], vl4);
                            MMA16816(o[mi][2*g+1], ph[mi], vh4 + 2);
                            MMA16816(o[mi][2*g+1], ph[mi], vl4 + 2);
                        }
                    }
                }
            }
        }
        __syncthreads();   // all warps done with stage kb before kb+2 overwrite
    }

    // ---- epilogue: y = O / l -> hi/lo halves into out-proj input buffers ----
    int b = bh >> 4;
    int h = bh & 15;
    int d0 = 2 * (lane & 3);
    #pragma unroll
    for (int mi = 0; mi < 2; mi++) {
        float inv0 = 1.0f / lrow[mi][0];
        float inv1 = 1.0f / lrow[mi][1];
        int t0 = qt * 128 + warp * 32 + mi * 16 + (lane >> 2);
        #pragma unroll
        for (int j = 0; j < 8; j++) {
            int d = 8 * j + d0;
            {
                float y0 = o[mi][j][0] * inv0, y1 = o[mi][j][1] * inv0;
                __half2 hh = __floats2half2_rn(y0, y1);
                float2 hf = __half22float2(hh);
                __half2 ll = __floats2half2_rn(y0 - hf.x, y1 - hf.y);
                size_t idx = ((size_t)(b * T_ + t0)) * C_ + h * HD_ + d;
                *(__half2*)(g_xh + idx) = hh;
                *(__half2*)(g_xl + idx) = ll;
            }
            {
                float y0 = o[mi][j][2] * inv1, y1 = o[mi][j][3] * inv1;
                __half2 hh = __floats2half2_rn(y0, y1);
                float2 hf = __half22float2(hh);
                __half2 ll = __floats2half2_rn(y0 - hf.x, y1 - hf.y);
                size_t idx = ((size_t)(b * T_ + t0 + 8)) * C_ + h * HD_ + d;
                *(__half2*)(g_xh + idx) = hh;
                *(__half2*)(g_xl + idx) = ll;
            }
        }
    }
}

// ---------------------------------------------------------------------------
extern "C" void kernel_launch(void* const* d_in, const int* in_sizes, int n_in,
                              void* d_out, int out_size)
{
    const float* x  = (const float*)d_in[0];
    const float* Wq = (const float*)d_in[1];
    const float* bq = (const float*)d_in[2];
    const float* Wk = (const float*)d_in[3];
    const float* bk = (const float*)d_in[4];
    const float* Wv = (const float*)d_in[5];
    const float* bv = (const float*)d_in[6];
    const float* Wp = (const float*)d_in[7];
    const float* bp = (const float*)d_in[8];
    float* out = (float*)d_out;

    __half *qh, *ql, *kh, *kl, *vh, *vl, *xh, *xl, *wh, *wl;
    cudaGetSymbolAddress((void**)&qh, g_qh);
    cudaGetSymbolAddress((void**)&ql, g_ql);
    cudaGetSymbolAddress((void**)&kh, g_kh);
    cudaGetSymbolAddress((void**)&kl, g_kl);
    cudaGetSymbolAddress((void**)&vh, g_vh);
    cudaGetSymbolAddress((void**)&vl, g_vl);
    cudaGetSymbolAddress((void**)&xh, g_xh);
    cudaGetSymbolAddress((void**)&xl, g_xl);
    cudaGetSymbolAddress((void**)&wh, g_wh);
    cudaGetSymbolAddress((void**)&wl, g_wl);

    cudaFuncSetAttribute(gemm_hmma<0>, cudaFuncAttributeMaxDynamicSharedMemorySize, GEMM_SMEM);
    cudaFuncSetAttribute(gemm_hmma<1>, cudaFuncAttributeMaxDynamicSharedMemorySize, GEMM_SMEM);
    cudaFuncSetAttribute(attn_tc, cudaFuncAttributeMaxDynamicSharedMemorySize, AT_SMEM);

    const int NX4 = NTOK * C_ / 4;     // 1M
    const int NW4 = C_ * C_ / 4;       // 256K
    cvt_split_all<<<(NX4 + 4*NW4 + 255)/256, 256>>>(
        (const float4*)x,
        (const float4*)Wq, (const float4*)Wk, (const float4*)Wv, (const float4*)Wp,
        (__half2*)xh, (__half2*)xl, (__half2*)wh, (__half2*)wl);

    const float QSCALE = 0.125f * 1.44269504088896f;   // 1/sqrt(64) * log2(e)

    dim3 qkv_grid(3*C_/128, NTOK/128);   // (24, 32)
    gemm_hmma<1><<<qkv_grid, 256, GEMM_SMEM>>>(
        xh, xl, wh, wl, bq, bk, bv, nullptr,
        qh, ql, kh, kl, vh, vl, QSCALE);

    attn_tc<<<dim3(T_/128, B_*H_), 128, AT_SMEM>>>();   // writes y hi/lo into xh/xl

    dim3 ggrid(C_/128, NTOK/128);        // (8, 32)
    gemm_hmma<0><<<ggrid, 256, GEMM_SMEM>>>(
        xh, xl, wh + 3*(size_t)C_*C_, wl + 3*(size_t)C_*C_, bp, nullptr, nullptr,
        out, nullptr, nullptr, nullptr, nullptr, nullptr, nullptr, 1.0f);
}

// round 11
// speedup vs baseline: 1.2816x; 1.1394x over previous
#include <cuda_runtime.h>
#include <cuda_fp16.h>
#include <math.h>
#include <stdint.h>

#define B_   2
#define T_   2048
#define C_   1024
#define H_   16
#define HD_  64
#define NTOK (B_*T_)   // 4096

// ---------------------------------------------------------------------------
// Scratch (__device__ globals; allocation-free rule)
// ---------------------------------------------------------------------------
__device__ __half g_qh[NTOK*C_], g_ql[NTOK*C_];
__device__ __half g_kh[NTOK*C_], g_kl[NTOK*C_];
__device__ __half g_vh[NTOK*C_], g_vl[NTOK*C_];
__device__ __half g_xh[NTOK*C_], g_xl[NTOK*C_];   // x hi (QKV input); later y hi/lo
__device__ __half g_wh[4*C_*C_], g_wl[4*C_*C_];   // Wq|Wk|Wv|Wp hi/lo

// ---------------------------------------------------------------------------
// PTX helpers (sm_80-baseline only — harness compiles for sm_103 w/o 'a')
// ---------------------------------------------------------------------------
__device__ __forceinline__ uint32_t smem_u32(const void* p) {
    uint32_t a;
    asm("{ .reg .u64 t; cvta.to.shared.u64 t, %1; cvt.u32.u64 %0, t; }"
        : "=r"(a) : "l"(p));
    return a;
}
__device__ __forceinline__ void cp16(uint32_t dst, const void* src) {
    asm volatile("cp.async.ca.shared.global [%0], [%1], 16;" :: "r"(dst), "l"(src));
}
#define CP_COMMIT()  asm volatile("cp.async.commit_group;" ::: "memory")
#define CP_WAIT(N)   asm volatile("cp.async.wait_group " #N ";" ::: "memory")

#define LDMX4(r, addr) \
    asm volatile("ldmatrix.sync.aligned.m8n8.x4.shared.b16 {%0,%1,%2,%3}, [%4];" \
        : "=r"((r)[0]), "=r"((r)[1]), "=r"((r)[2]), "=r"((r)[3]) : "r"(addr))
#define LDMX4T(r, addr) \
    asm volatile("ldmatrix.sync.aligned.m8n8.x4.trans.shared.b16 {%0,%1,%2,%3}, [%4];" \
        : "=r"((r)[0]), "=r"((r)[1]), "=r"((r)[2]), "=r"((r)[3]) : "r"(addr))

#define MMA16816(d, a, b) \
    asm volatile("mma.sync.aligned.m16n8k16.row.col.f32.f16.f16.f32 " \
        "{%0,%1,%2,%3}, {%4,%5,%6,%7}, {%8,%9}, {%0,%1,%2,%3};" \
        : "+f"((d)[0]), "+f"((d)[1]), "+f"((d)[2]), "+f"((d)[3]) \
        : "r"((a)[0]), "r"((a)[1]), "r"((a)[2]), "r"((a)[3]), \
          "r"((b)[0]), "r"((b)[1]))

__device__ __forceinline__ float ex2(float x) {
    float r;
    asm("ex2.approx.ftz.f32 %0, %1;" : "=f"(r) : "f"(x));
    return r;
}
__device__ __forceinline__ uint32_t packh2(float a, float b) {
    __half2 h = __floats2half2_rn(a, b);
    return *reinterpret_cast<uint32_t*>(&h);
}

// ---------------------------------------------------------------------------
// fp32 -> fp16 split conversion — x (hi only) and all 4 weights (hi+lo), ONE launch
// ---------------------------------------------------------------------------
__global__ void __launch_bounds__(256)
cvt_split_all(const float4* __restrict__ x,
              const float4* __restrict__ w0, const float4* __restrict__ w1,
              const float4* __restrict__ w2, const float4* __restrict__ w3,
              __half2* __restrict__ xhi,
              __half2* __restrict__ whi, __half2* __restrict__ wlo)
{
    const int NX4 = NTOK * C_ / 4;   // 1048576
    const int NW4 = C_ * C_ / 4;     // 262144 = 2^18
    int i = blockIdx.x * blockDim.x + threadIdx.x;
    if (i < NX4) {
        float4 f = x[i];
        xhi[2*i]   = __floats2half2_rn(f.x, f.y);
        xhi[2*i+1] = __floats2half2_rn(f.z, f.w);
        return;
    }
    int j = i - NX4;
    if (j >= 4 * NW4) return;
    int mid = j >> 18;
    int off = j & (NW4 - 1);
    const float4* src = ((mid == 0) ? w0 : (mid == 1) ? w1 : (mid == 2) ? w2 : w3) + off;
    float4 f = *src;
    __half2 h01 = __floats2half2_rn(f.x, f.y);
    __half2 h23 = __floats2half2_rn(f.z, f.w);
    float2 b01 = __half22float2(h01);
    float2 b23 = __half22float2(h23);
    whi[2*j]   = h01;  whi[2*j+1] = h23;
    wlo[2*j]   = __floats2half2_rn(f.x - b01.x, f.y - b01.y);
    wlo[2*j+1] = __floats2half2_rn(f.z - b23.x, f.w - b23.y);
}

// ---------------------------------------------------------------------------
// QKV GEMM (2-term split: Ah*(Bh+Bl)). CTA tile 128x128 over N=3072.
// Stage = Ah(16K)+Bh(16K)+Bl(16K) = 48 KB; 2 stages = 96 KB -> 2 CTAs/SM.
// Head-split hi/lo fp16 outputs, bias + per-matrix scale fused.
// ---------------------------------------------------------------------------
#define QKV_SMEM (2*49152)

__device__ __forceinline__ void load_stage_qkv(
    uint32_t sb, const __half* __restrict__ Ah,
    const __half* __restrict__ Bh, const __half* __restrict__ Bl,
    int m0, int n0, int k0, int tid)
{
    #pragma unroll
    for (int i = 0; i < 4; i++) {
        int idx = tid + i * 256;
        int r = idx >> 3, u = idx & 7;
        uint32_t doff = r * 128 + ((u ^ (r & 7)) << 4);
        size_t aoff = (size_t)(m0 + r) * C_ + k0 + u * 8;
        size_t boff = (size_t)(n0 + r) * C_ + k0 + u * 8;
        cp16(sb +         doff, Ah + aoff);
        cp16(sb + 16384 + doff, Bh + boff);
        cp16(sb + 32768 + doff, Bl + boff);
    }
}

__global__ void __launch_bounds__(256, 2)
gemm_qkv(const __half* __restrict__ Ah,
         const __half* __restrict__ Bh, const __half* __restrict__ Bl,
         const float* __restrict__ b0, const float* __restrict__ b1,
         const float* __restrict__ b2,
         __half* __restrict__ o0h, __half* __restrict__ o0l,
         __half* __restrict__ o1h, __half* __restrict__ o1l,
         __half* __restrict__ o2h, __half* __restrict__ o2l,
         float scale0)
{
    extern __shared__ __align__(1024) char smem[];
    uint32_t sbase = smem_u32(smem);
    const int tid  = threadIdx.x;
    const int lane = tid & 31;
    const int warp = tid >> 5;
    const int wm   = warp >> 2;
    const int wn   = warp & 3;
    const int m0   = blockIdx.y * 128;
    const int n0   = blockIdx.x * 128;

    float acc[4][4][4];
    #pragma unroll
    for (int i = 0; i < 4; i++)
        #pragma unroll
        for (int j = 0; j < 4; j++)
            #pragma unroll
            for (int k = 0; k < 4; k++) acc[i][j][k] = 0.f;

    load_stage_qkv(sbase, Ah, Bh, Bl, m0, n0, 0, tid);
    CP_COMMIT();

    for (int kt = 0; kt < 16; kt++) {
        if (kt + 1 < 16) {
            load_stage_qkv(sbase + ((kt + 1) & 1) * 49152, Ah, Bh, Bl,
                           m0, n0, (kt + 1) * 64, tid);
            CP_COMMIT();
            CP_WAIT(1);
        } else {
            CP_WAIT(0);
        }
        __syncthreads();

        uint32_t sb = sbase + (kt & 1) * 49152;

        #pragma unroll
        for (int ks = 0; ks < 4; ks++) {
            uint32_t ah[4][4];
            {
                int arow = wm * 64 + (lane & 15);
                int aku  = ks * 2 + (lane >> 4);
                #pragma unroll
                for (int mi = 0; mi < 4; mi++) {
                    int r = arow + mi * 16;
                    LDMX4(ah[mi], sb + r * 128 + ((aku ^ (r & 7)) << 4));
                }
            }
            uint32_t bhf[4][2], blf[4][2];
            {
                int brow0 = wn * 32 + ((lane >> 4) << 3) + (lane & 7);
                int bku   = ks * 2 + ((lane >> 3) & 1);
                #pragma unroll
                for (int nj2 = 0; nj2 < 2; nj2++) {
                    int r = brow0 + nj2 * 16;
                    uint32_t addr = sb + 16384 + r * 128 + ((bku ^ (r & 7)) << 4);
                    uint32_t t[4];
                    LDMX4(t, addr);
                    bhf[2*nj2][0] = t[0]; bhf[2*nj2][1] = t[1];
                    bhf[2*nj2+1][0] = t[2]; bhf[2*nj2+1][1] = t[3];
                    LDMX4(t, addr + 16384);
                    blf[2*nj2][0] = t[0]; blf[2*nj2][1] = t[1];
                    blf[2*nj2+1][0] = t[2]; blf[2*nj2+1][1] = t[3];
                }
            }
            #pragma unroll
            for (int mi = 0; mi < 4; mi++)
                #pragma unroll
                for (int nj = 0; nj < 4; nj++) {
                    MMA16816(acc[mi][nj], ah[mi], bhf[nj]);
                    MMA16816(acc[mi][nj], ah[mi], blf[nj]);
                }
        }
        __syncthreads();
    }

    const int r0 = lane >> 2;
    const int c0 = (lane & 3) * 2;
    int mid = n0 >> 10;
    const float* bias = (mid == 0) ? b0 : (mid == 1) ? b1 : b2;
    __half* oh = (mid == 0) ? o0h : (mid == 1) ? o1h : o2h;
    __half* ol = (mid == 0) ? o0l : (mid == 1) ? o1l : o2l;
    float scale = (mid == 0) ? scale0 : 1.0f;

    #pragma unroll
    for (int mi = 0; mi < 4; mi++) {
        #pragma unroll
        for (int nj = 0; nj < 4; nj++) {
            int nl = (n0 & 1023) + wn * 32 + nj * 8 + c0;
            float2 bv = *(const float2*)(bias + nl);
            #pragma unroll
            for (int h2 = 0; h2 < 2; h2++) {
                int m = m0 + wm * 64 + mi * 16 + r0 + h2 * 8;
                float v0 = (acc[mi][nj][h2*2+0] + bv.x) * scale;
                float v1 = (acc[mi][nj][h2*2+1] + bv.y) * scale;
                __half2 hh = __floats2half2_rn(v0, v1);
                float2 hf = __half22float2(hh);
                __half2 ll = __floats2half2_rn(v0 - hf.x, v1 - hf.y);
                int b = m >> 11, t = m & (T_ - 1);
                int h = nl >> 6, d = nl & 63;
                size_t idx = (((size_t)(b * H_ + h)) * T_ + t) * HD_ + d;
                *(__half2*)(oh + idx) = hh;
                *(__half2*)(ol + idx) = ll;
            }
        }
    }
}

// ---------------------------------------------------------------------------
// Out-projection GEMM: full 3-term split (error appears directly in output).
// CTA tile 128x128, BK=64, 2-stage, 128 KB smem.
// ---------------------------------------------------------------------------
#define GEMM_SMEM (2*65536)

__device__ __forceinline__ void load_stage(
    uint32_t sb,
    const __half* __restrict__ Ah, const __half* __restrict__ Al,
    const __half* __restrict__ Bh, const __half* __restrict__ Bl,
    int m0, int n0, int k0, int tid)
{
    #pragma unroll
    for (int i = 0; i < 4; i++) {
        int idx = tid + i * 256;
        int r = idx >> 3, u = idx & 7;
        uint32_t doff = r * 128 + ((u ^ (r & 7)) << 4);
        size_t aoff = (size_t)(m0 + r) * C_ + k0 + u * 8;
        size_t boff = (size_t)(n0 + r) * C_ + k0 + u * 8;
        cp16(sb +         doff, Ah + aoff);
        cp16(sb + 16384 + doff, Al + aoff);
        cp16(sb + 32768 + doff, Bh + boff);
        cp16(sb + 49152 + doff, Bl + boff);
    }
}

__global__ void __launch_bounds__(256)
gemm_out(const __half* __restrict__ Ah, const __half* __restrict__ Al,
         const __half* __restrict__ Bh, const __half* __restrict__ Bl,
         const float* __restrict__ bias, float* __restrict__ outf)
{
    extern __shared__ __align__(1024) char smem[];
    uint32_t sbase = smem_u32(smem);
    const int tid  = threadIdx.x;
    const int lane = tid & 31;
    const int warp = tid >> 5;
    const int wm   = warp >> 2;
    const int wn   = warp & 3;
    const int m0   = blockIdx.y * 128;
    const int n0   = blockIdx.x * 128;

    float acc[4][4][4];
    #pragma unroll
    for (int i = 0; i < 4; i++)
        #pragma unroll
        for (int j = 0; j < 4; j++)
            #pragma unroll
            for (int k = 0; k < 4; k++) acc[i][j][k] = 0.f;

    load_stage(sbase, Ah, Al, Bh, Bl, m0, n0, 0, tid);
    CP_COMMIT();

    for (int kt = 0; kt < 16; kt++) {
        if (kt + 1 < 16) {
            load_stage(sbase + ((kt + 1) & 1) * 65536, Ah, Al, Bh, Bl,
                       m0, n0, (kt + 1) * 64, tid);
            CP_COMMIT();
            CP_WAIT(1);
        } else {
            CP_WAIT(0);
        }
        __syncthreads();

        uint32_t sb = sbase + (kt & 1) * 65536;

        #pragma unroll
        for (int ks = 0; ks < 4; ks++) {
            uint32_t ah[4][4], al[4][4];
            {
                int arow = wm * 64 + (lane & 15);
                int aku  = ks * 2 + (lane >> 4);
                #pragma unroll
                for (int mi = 0; mi < 4; mi++) {
                    int r = arow + mi * 16;
                    uint32_t addr = sb + r * 128 + ((aku ^ (r & 7)) << 4);
                    LDMX4(ah[mi], addr);
                    LDMX4(al[mi], addr + 16384);
                }
            }
            uint32_t bhf[4][2], blf[4][2];
            {
                int brow0 = wn * 32 + ((lane >> 4) << 3) + (lane & 7);
                int bku   = ks * 2 + ((lane >> 3) & 1);
                #pragma unroll
                for (int nj2 = 0; nj2 < 2; nj2++) {
                    int r = brow0 + nj2 * 16;
                    uint32_t addr = sb + 32768 + r * 128 + ((bku ^ (r & 7)) << 4);
                    uint32_t t[4];
                    LDMX4(t, addr);
                    bhf[2*nj2][0] = t[0]; bhf[2*nj2][1] = t[1];
                    bhf[2*nj2+1][0] = t[2]; bhf[2*nj2+1][1] = t[3];
                    LDMX4(t, addr + 16384);
                    blf[2*nj2][0] = t[0]; blf[2*nj2][1] = t[1];
                    blf[2*nj2+1][0] = t[2]; blf[2*nj2+1][1] = t[3];
                }
            }
            #pragma unroll
            for (int mi = 0; mi < 4; mi++)
                #pragma unroll
                for (int nj = 0; nj < 4; nj++) {
                    MMA16816(acc[mi][nj], ah[mi], bhf[nj]);
                    MMA16816(acc[mi][nj], al[mi], bhf[nj]);
                    MMA16816(acc[mi][nj], ah[mi], blf[nj]);
                }
        }
        __syncthreads();
    }

    const int r0 = lane >> 2;
    const int c0 = (lane & 3) * 2;
    #pragma unroll
    for (int mi = 0; mi < 4; mi++) {
        #pragma unroll
        for (int nj = 0; nj < 4; nj++) {
            int nl = n0 + wn * 32 + nj * 8 + c0;
            float2 bv = *(const float2*)(bias + nl);
            #pragma unroll
            for (int h2 = 0; h2 < 2; h2++) {
                int m = m0 + wm * 64 + mi * 16 + r0 + h2 * 8;
                float2 o;
                o.x = acc[mi][nj][h2*2+0] + bv.x;
                o.y = acc[mi][nj][h2*2+1] + bv.y;
                *(float2*)(outf + (size_t)m * C_ + nl) = o;
            }
        }
    }
}

// ---------------------------------------------------------------------------
// Tensor-core flash attention v6 (unchanged from R10): 4 warps x 32 q-rows,
// 64-key blocks, 2-term splits. smem 80 KB -> 2 CTAs/SM.
// ---------------------------------------------------------------------------
#define AT_SMEM (16384 + 2*32768)

__global__ void __launch_bounds__(128, 2) attn_tc()
{
    extern __shared__ __align__(1024) char smem[];
    uint32_t sb = smem_u32(smem);
    const int tid  = threadIdx.x;
    const int lane = tid & 31;
    const int warp = tid >> 5;                              // 0..3
    const int qt   = (int)gridDim.x - 1 - (int)blockIdx.x;  // heavy first
    const int bh   = blockIdx.y;
    const int nkb  = 2 * qt + 2;                            // 64-key blocks

    const __half* qhp = g_qh + ((size_t)bh * T_ + qt * 128) * HD_;
    const __half* khp = g_kh + (size_t)bh * T_ * HD_;
    const __half* klp = g_kl + (size_t)bh * T_ * HD_;
    const __half* vhp = g_vh + (size_t)bh * T_ * HD_;
    const __half* vlp = g_vl + (size_t)bh * T_ * HD_;

    #pragma unroll
    for (int i = 0; i < 8; i++) {
        int idx = tid + i * 128;
        int r = idx >> 3, u = idx & 7;
        cp16(sb + r * 128 + ((u ^ (r & 7)) << 4), qhp + (size_t)r * HD_ + u * 8);
    }
    CP_COMMIT();

    auto load_kv = [&](int stage, int kb) {
        uint32_t st = sb + 16384 + stage * 32768;
        #pragma unroll
        for (int i = 0; i < 16; i++) {
            int idx = tid + i * 128;
            int a = idx >> 9;
            int w = idx & 511;
            int r = w >> 3, u = w & 7;
            const __half* src;
            switch (a) {
                case 0: src = khp; break;
                case 1: src = klp; break;
                case 2: src = vhp; break;
                default: src = vlp; break;
            }
            src += ((size_t)(kb * 64 + r)) * HD_ + u * 8;
            cp16(st + a * 8192 + r * 128 + ((u ^ (r & 7)) << 4), src);
        }
    };
    load_kv(0, 0);
    CP_COMMIT();

    CP_WAIT(1);
    __syncthreads();
    uint32_t qfh[2][4][4];
    #pragma unroll
    for (int mi = 0; mi < 2; mi++) {
        int arow = warp * 32 + mi * 16 + (lane & 15);
        #pragma unroll
        for (int ks = 0; ks < 4; ks++) {
            int u = ks * 2 + (lane >> 4);
            LDMX4(qfh[mi][ks], sb + arow * 128 + ((u ^ (arow & 7)) << 4));
        }
    }

    float o[2][8][4];
    #pragma unroll
    for (int mi = 0; mi < 2; mi++)
        #pragma unroll
        for (int j = 0; j < 8; j++)
            #pragma unroll
            for (int e = 0; e < 4; e++) o[mi][j][e] = 0.f;
    float mrow[2][2] = {{-1e30f, -1e30f}, {-1e30f, -1e30f}};
    float lrow[2][2] = {{0.f, 0.f}, {0.f, 0.f}};

    for (int kb = 0; kb < nkb; kb++) {
        if (kb + 1 < nkb) { load_kv((kb + 1) & 1, kb + 1); CP_COMMIT(); CP_WAIT(1); }
        else              { CP_WAIT(0); }
        __syncthreads();

        const bool maskblk = (kb >= 2 * qt);
        const int  kloc    = (kb - 2 * qt) * 64;
        uint32_t st = sb + 16384 + (kb & 1) * 32768;
        uint32_t sv = st + 16384;

        float s[2][8][4];
        #pragma unroll
        for (int mi = 0; mi < 2; mi++)
            #pragma unroll
            for (int j = 0; j < 8; j++)
                #pragma unroll
                for (int e = 0; e < 4; e++) s[mi][j][e] = 0.f;

        #pragma unroll
        for (int ks = 0; ks < 4; ks++) {
            #pragma unroll
            for (int g = 0; g < 4; g++) {
                if (!maskblk || kloc + 16 * g <= 32 * warp + 31) {
                    int brow = g * 16 + ((lane >> 4) << 3) + (lane & 7);
                    int bku  = ks * 2 + ((lane >> 3) & 1);
                    uint32_t addr = st + brow * 128 + ((bku ^ (brow & 7)) << 4);
                    uint32_t kh4[4], kl4[4];
                    LDMX4(kh4, addr);
                    LDMX4(kl4, addr + 8192);
                    #pragma unroll
                    for (int mi = 0; mi < 2; mi++) {
                        if (!maskblk || kloc + 16 * g <= 32 * warp + mi * 16 + 15) {
                            MMA16816(s[mi][2*g],   qfh[mi][ks], kh4);
                            MMA16816(s[mi][2*g],   qfh[mi][ks], kl4);
                            MMA16816(s[mi][2*g+1], qfh[mi][ks], kh4 + 2);
                            MMA16816(s[mi][2*g+1], qfh[mi][ks], kl4 + 2);
                        }
                    }
                }
            }
        }

        if (maskblk) {
            #pragma unroll
            for (int mi = 0; mi < 2; mi++) {
                int rbase = 32 * warp + 16 * mi + (lane >> 2);
                int cbase = kloc + 2 * (lane & 3);
                #pragma unroll
                for (int j = 0; j < 8; j++) {
                    int c = cbase + 8 * j;
                    if (c     > rbase)     s[mi][j][0] = -1e30f;
                    if (c + 1 > rbase)     s[mi][j][1] = -1e30f;
                    if (c     > rbase + 8) s[mi][j][2] = -1e30f;
                    if (c + 1 > rbase + 8) s[mi][j][3] = -1e30f;
                }
            }
        }

        #pragma unroll
        for (int mi = 0; mi < 2; mi++) {
            float mloc0 = -1e30f, mloc1 = -1e30f;
            #pragma unroll
            for (int j = 0; j < 8; j++) {
                mloc0 = fmaxf(mloc0, fmaxf(s[mi][j][0], s[mi][j][1]));
                mloc1 = fmaxf(mloc1, fmaxf(s[mi][j][2], s[mi][j][3]));
            }
            #pragma unroll
            for (int off = 1; off < 4; off <<= 1) {
                mloc0 = fmaxf(mloc0, __shfl_xor_sync(0xffffffffu, mloc0, off));
                mloc1 = fmaxf(mloc1, __shfl_xor_sync(0xffffffffu, mloc1, off));
            }
            float mn0 = fmaxf(mrow[mi][0], mloc0);
            float mn1 = fmaxf(mrow[mi][1], mloc1);
            float cr0 = ex2(mrow[mi][0] - mn0);
            float cr1 = ex2(mrow[mi][1] - mn1);
            mrow[mi][0] = mn0; mrow[mi][1] = mn1;

            float sum0 = 0.f, sum1 = 0.f;
            #pragma unroll
            for (int j = 0; j < 8; j++) {
                s[mi][j][0] = ex2(s[mi][j][0] - mn0); sum0 += s[mi][j][0];
                s[mi][j][1] = ex2(s[mi][j][1] - mn0); sum0 += s[mi][j][1];
                s[mi][j][2] = ex2(s[mi][j][2] - mn1); sum1 += s[mi][j][2];
                s[mi][j][3] = ex2(s[mi][j][3] - mn1); sum1 += s[mi][j][3];
            }
            #pragma unroll
            for (int off = 1; off < 4; off <<= 1) {
                sum0 += __shfl_xor_sync(0xffffffffu, sum0, off);
                sum1 += __shfl_xor_sync(0xffffffffu, sum1, off);
            }
            lrow[mi][0] = lrow[mi][0] * cr0 + sum0;
            lrow[mi][1] = lrow[mi][1] * cr1 + sum1;

            #pragma unroll
            for (int j = 0; j < 8; j++) {
                o[mi][j][0] *= cr0; o[mi][j][1] *= cr0;
                o[mi][j][2] *= cr1; o[mi][j][3] *= cr1;
            }
        }

        #pragma unroll
        for (int kk = 0; kk < 4; kk++) {
            if (!maskblk || kloc + 16 * kk <= 32 * warp + 31) {
                uint32_t ph[2][4];
                #pragma unroll
                for (int mi = 0; mi < 2; mi++) {
                    ph[mi][0] = packh2(s[mi][2*kk][0],   s[mi][2*kk][1]);
                    ph[mi][1] = packh2(s[mi][2*kk][2],   s[mi][2*kk][3]);
                    ph[mi][2] = packh2(s[mi][2*kk+1][0], s[mi][2*kk+1][1]);
                    ph[mi][3] = packh2(s[mi][2*kk+1][2], s[mi][2*kk+1][3]);
                }
                int vrow = kk * 16 + ((lane >> 3) & 1) * 8 + (lane & 7);
                #pragma unroll
                for (int g = 0; g < 4; g++) {
                    int vu = 2 * g + (lane >> 4);
                    uint32_t addr = sv + vrow * 128 + ((vu ^ (vrow & 7)) << 4);
                    uint32_t vh4[4], vl4[4];
                    LDMX4T(vh4, addr);
                    LDMX4T(vl4, addr + 8192);
                    #pragma unroll
                    for (int mi = 0; mi < 2; mi++) {
                        if (!maskblk || kloc + 16 * kk <= 32 * warp + mi * 16 + 15) {
                            MMA16816(o[mi][2*g],   ph[mi], vh4);
                            MMA16816(o[mi][2*g],   ph[mi], vl4);
                            MMA16816(o[mi][2*g+1], ph[mi], vh4 + 2);
                            MMA16816(o[mi][2*g+1], ph[mi], vl4 + 2);
                        }
                    }
                }
            }
        }
        __syncthreads();
    }

    int b = bh >> 4;
    int h = bh & 15;
    int d0 = 2 * (lane & 3);
    #pragma unroll
    for (int mi = 0; mi < 2; mi++) {
        float inv0 = 1.0f / lrow[mi][0];
        float inv1 = 1.0f / lrow[mi][1];
        int t0 = qt * 128 + warp * 32 + mi * 16 + (lane >> 2);
        #pragma unroll
        for (int j = 0; j < 8; j++) {
            int d = 8 * j + d0;
            {
                float y0 = o[mi][j][0] * inv0, y1 = o[mi][j][1] * inv0;
                __half2 hh = __floats2half2_rn(y0, y1);
                float2 hf = __half22float2(hh);
                __half2 ll = __floats2half2_rn(y0 - hf.x, y1 - hf.y);
                size_t idx = ((size_t)(b * T_ + t0)) * C_ + h * HD_ + d;
                *(__half2*)(g_xh + idx) = hh;
                *(__half2*)(g_xl + idx) = ll;
            }
            {
                float y0 = o[mi][j][2] * inv1, y1 = o[mi][j][3] * inv1;
                __half2 hh = __floats2half2_rn(y0, y1);
                float2 hf = __half22float2(hh);
                __half2 ll = __floats2half2_rn(y0 - hf.x, y1 - hf.y);
                size_t idx = ((size_t)(b * T_ + t0 + 8)) * C_ + h * HD_ + d;
                *(__half2*)(g_xh + idx) = hh;
                *(__half2*)(g_xl + idx) = ll;
            }
        }
    }
}

// ---------------------------------------------------------------------------
extern "C" void kernel_launch(void* const* d_in, const int* in_sizes, int n_in,
                              void* d_out, int out_size)
{
    const float* x  = (const float*)d_in[0];
    const float* Wq = (const float*)d_in[1];
    const float* bq = (const float*)d_in[2];
    const float* Wk = (const float*)d_in[3];
    const float* bk = (const float*)d_in[4];
    const float* Wv = (const float*)d_in[5];
    const float* bv = (const float*)d_in[6];
    const float* Wp = (const float*)d_in[7];
    const float* bp = (const float*)d_in[8];
    float* out = (float*)d_out;

    __half *qh, *ql, *kh, *kl, *vh, *vl, *xh, *xl, *wh, *wl;
    cudaGetSymbolAddress((void**)&qh, g_qh);
    cudaGetSymbolAddress((void**)&ql, g_ql);
    cudaGetSymbolAddress((void**)&kh, g_kh);
    cudaGetSymbolAddress((void**)&kl, g_kl);
    cudaGetSymbolAddress((void**)&vh, g_vh);
    cudaGetSymbolAddress((void**)&vl, g_vl);
    cudaGetSymbolAddress((void**)&xh, g_xh);
    cudaGetSymbolAddress((void**)&xl, g_xl);
    cudaGetSymbolAddress((void**)&wh, g_wh);
    cudaGetSymbolAddress((void**)&wl, g_wl);

    cudaFuncSetAttribute(gemm_qkv, cudaFuncAttributeMaxDynamicSharedMemorySize, QKV_SMEM);
    cudaFuncSetAttribute(gemm_out, cudaFuncAttributeMaxDynamicSharedMemorySize, GEMM_SMEM);
    cudaFuncSetAttribute(attn_tc,  cudaFuncAttributeMaxDynamicSharedMemorySize, AT_SMEM);

    const int NX4 = NTOK * C_ / 4;     // 1M
    const int NW4 = C_ * C_ / 4;       // 256K
    cvt_split_all<<<(NX4 + 4*NW4 + 255)/256, 256>>>(
        (const float4*)x,
        (const float4*)Wq, (const float4*)Wk, (const float4*)Wv, (const float4*)Wp,
        (__half2*)xh, (__half2*)wh, (__half2*)wl);

    const float QSCALE = 0.125f * 1.44269504088896f;   // 1/sqrt(64) * log2(e)

    dim3 qkv_grid(3*C_/128, NTOK/128);   // (24, 32)
    gemm_qkv<<<qkv_grid, 256, QKV_SMEM>>>(
        xh, wh, wl, bq, bk, bv,
        qh, ql, kh, kl, vh, vl, QSCALE);

    attn_tc<<<dim3(T_/128, B_*H_), 128, AT_SMEM>>>();   // writes y hi/lo into xh/xl

    dim3 ggrid(C_/128, NTOK/128);        // (8, 32)
    gemm_out<<<ggrid, 256, GEMM_SMEM>>>(
        xh, xl, wh + 3*(size_t)C_*C_, wl + 3*(size_t)C_*C_, bp, out);
}